// round 1
// baseline (speedup 1.0000x reference)
#include <cuda_runtime.h>
#include <math.h>

#define BSZ 64
#define NPIX 196
#define ENCD 512
#define DD 512
#define VV 32000
#define TT 50
#define ML 51

// ---------------- scratch (static device globals; no runtime alloc) ----------
__device__ float d_enc_s[BSZ*NPIX*ENCD];   // sorted encoder features
__device__ float d_ea[BSZ*NPIX*ENCD];      // enc @ W_enc_attn^T + b
__device__ float d_mean[BSZ*ENCD];
__device__ float d_h[BSZ*DD];
__device__ float d_c[BSZ*DD];
__device__ float d_ctx[BSZ*ENCD];
__device__ float d_gates[BSZ*4*DD];
__device__ int   d_order[BSZ];
__device__ int   d_declen[BSZ];
__device__ int   d_caps_s[BSZ*ML];
__device__ int   d_nact[TT];

// ---------------- helpers ----------------------------------------------------
__device__ __forceinline__ float warp_sum(float v) {
    #pragma unroll
    for (int o = 16; o > 0; o >>= 1) v += __shfl_down_sync(0xffffffffu, v, o);
    return v;
}
__device__ __forceinline__ float warp_max(float v) {
    #pragma unroll
    for (int o = 16; o > 0; o >>= 1) v = fmaxf(v, __shfl_down_sync(0xffffffffu, v, o));
    return v;
}
__device__ __forceinline__ float sigmoidf_(float x) { return 1.0f / (1.0f + __expf(-x)); }

// ---------------- sort (stable, descending cap_len) ---------------------------
__global__ void sort_kernel(const int* __restrict__ cap_len,
                            const int* __restrict__ caps,
                            float* __restrict__ out_caps,
                            float* __restrict__ out_declen,
                            float* __restrict__ out_order) {
    int i = threadIdx.x;  // 64 threads
    int cl = cap_len[i];
    int r = 0;
    for (int j = 0; j < BSZ; j++) {
        int cj = cap_len[j];
        if (cj > cl || (cj == cl && j < i)) r++;
    }
    d_order[r]  = i;
    d_declen[r] = cl - 1;
    __syncthreads();
    out_order[i]  = (float)d_order[i];
    out_declen[i] = (float)d_declen[i];
    int src = d_order[i];
    for (int tt = 0; tt < ML; tt++) {
        int tok = caps[src*ML + tt];
        d_caps_s[i*ML + tt] = tok;
        out_caps[i*ML + tt] = (float)tok;
    }
    if (i < TT) {
        int cnt = 0;
        for (int j = 0; j < BSZ; j++) if (d_declen[j] > i) cnt++;
        d_nact[i] = cnt;
    }
}

// ---------------- reorder encoder + per-batch pixel mean ----------------------
__global__ __launch_bounds__(256) void reorder_mean_kernel(const float* __restrict__ enc) {
    int b = blockIdx.x;
    int tid = threadIdx.x;  // 256
    int src = d_order[b];
    const float* Ein = enc + (size_t)src*NPIX*ENCD;
    float* Eo = d_enc_s + (size_t)b*NPIX*ENCD;
    float s0 = 0.f, s1 = 0.f;
    for (int p = 0; p < NPIX; p++) {
        float v0 = Ein[p*ENCD + tid];
        float v1 = Ein[p*ENCD + tid + 256];
        Eo[p*ENCD + tid]       = v0;
        Eo[p*ENCD + tid + 256] = v1;
        s0 += v0; s1 += v1;
    }
    d_mean[b*ENCD + tid]       = s0 * (1.0f/NPIX);
    d_mean[b*ENCD + tid + 256] = s1 * (1.0f/NPIX);
}

// ---------------- generic 64x64 tiled GEMM: C = A @ W^T + bias ---------------
// sel: 0 -> A=d_enc_s, C=d_ea ; 1 -> A=d_mean, C=d_h ; 2 -> A=d_mean, C=d_c
__global__ __launch_bounds__(256) void gemm64_kernel(int sel,
        const float* __restrict__ Wmat, const float* __restrict__ bias,
        int K, int N) {
    const float* Amat = (sel == 0) ? d_enc_s : d_mean;
    float*       Cmat = (sel == 0) ? d_ea : ((sel == 1) ? d_h : d_c);
    __shared__ float sA[32][64];
    __shared__ float sW[32][64];
    int tid = threadIdx.x;
    int tx = tid & 15, ty = tid >> 4;
    int m0 = blockIdx.y * 64;
    int n0 = blockIdx.x * 64;
    float acc[4][4] = {};
    for (int k0 = 0; k0 < K; k0 += 32) {
        #pragma unroll
        for (int u = 0; u < 2; u++) {
            int f4i = tid + u*256;
            int m  = f4i >> 3;
            int kk = (f4i & 7) << 2;
            float4 a = *(const float4*)&Amat[(size_t)(m0+m)*K + k0 + kk];
            sA[kk][m] = a.x; sA[kk+1][m] = a.y; sA[kk+2][m] = a.z; sA[kk+3][m] = a.w;
            float4 w = *(const float4*)&Wmat[(size_t)(n0+m)*K + k0 + kk];
            sW[kk][m] = w.x; sW[kk+1][m] = w.y; sW[kk+2][m] = w.z; sW[kk+3][m] = w.w;
        }
        __syncthreads();
        #pragma unroll
        for (int k = 0; k < 32; k++) {
            float4 a = *(const float4*)&sA[k][ty*4];
            float4 w = *(const float4*)&sW[k][tx*4];
            float av[4] = {a.x, a.y, a.z, a.w};
            float wv[4] = {w.x, w.y, w.z, w.w};
            #pragma unroll
            for (int i = 0; i < 4; i++)
                #pragma unroll
                for (int j = 0; j < 4; j++)
                    acc[i][j] += av[i] * wv[j];
        }
        __syncthreads();
    }
    #pragma unroll
    for (int i = 0; i < 4; i++) {
        int m = m0 + ty*4 + i;
        #pragma unroll
        for (int j = 0; j < 4; j++) {
            int n = n0 + tx*4 + j;
            Cmat[(size_t)m*N + n] = acc[i][j] + bias[n];
        }
    }
}

// ---------------- fused attention step (da, gate, scores, softmax, ctx) -------
__global__ __launch_bounds__(256) void attn_kernel(int t,
        const float* __restrict__ Wd, const float* __restrict__ bd,
        const float* __restrict__ wf, const float* __restrict__ bf_scalar,
        const float* __restrict__ Wg, const float* __restrict__ bg,
        float* __restrict__ out_alphas) {
    int b = blockIdx.x;
    if (t >= d_declen[b]) return;   // inactive: outputs already zero, h/c unused
    int tid  = threadIdx.x;
    int lane = tid & 31, warp = tid >> 5;   // 8 warps

    __shared__ float sh_h[512], sh_da[512], sh_g[512], sh_wf[512];
    __shared__ float sc[NPIX];
    __shared__ float red_m[8], red_s[8], bc[2];

    sh_h[tid]       = d_h[b*512 + tid];
    sh_h[tid + 256] = d_h[b*512 + tid + 256];
    sh_wf[tid]       = wf[tid];
    sh_wf[tid + 256] = wf[tid + 256];
    __syncthreads();

    // da[d] = h @ Wd[d,:] + bd[d];  gate[d] = sigmoid(h @ Wg[d,:] + bg[d])
    for (int d = warp*64; d < warp*64 + 64; d++) {
        float s1 = 0.f, s2 = 0.f;
        #pragma unroll
        for (int j = 0; j < 16; j++) {
            int k = lane + j*32;
            float hk = sh_h[k];
            s1 += hk * Wd[d*512 + k];
            s2 += hk * Wg[d*512 + k];
        }
        s1 = warp_sum(s1);
        s2 = warp_sum(s2);
        if (lane == 0) {
            sh_da[d] = s1 + bd[d];
            sh_g[d]  = sigmoidf_(s2 + bg[d]);
        }
    }
    __syncthreads();

    // scores[p] = relu(ea[b,p,:] + da) . wf + b_full
    const float* eab = d_ea + (size_t)b*NPIX*512;
    float bfull = bf_scalar[0];
    for (int p = warp; p < NPIX; p += 8) {
        float s = 0.f;
        #pragma unroll
        for (int j = 0; j < 16; j++) {
            int k = lane + j*32;
            float v = eab[p*512 + k] + sh_da[k];
            v = v > 0.f ? v : 0.f;
            s += v * sh_wf[k];
        }
        s = warp_sum(s);
        if (lane == 0) sc[p] = s + bfull;
    }
    __syncthreads();

    // softmax over 196
    float v = (tid < NPIX) ? sc[tid] : -1e30f;
    float wm = warp_max(v);
    if (lane == 0) red_m[warp] = wm;
    __syncthreads();
    if (tid == 0) {
        float mm = red_m[0];
        #pragma unroll
        for (int i = 1; i < 8; i++) mm = fmaxf(mm, red_m[i]);
        bc[0] = mm;
    }
    __syncthreads();
    float gmax = bc[0];
    float e = (tid < NPIX) ? __expf(v - gmax) : 0.f;
    float ws = warp_sum(e);
    if (lane == 0) red_s[warp] = ws;
    __syncthreads();
    if (tid == 0) {
        float ss = 0.f;
        #pragma unroll
        for (int i = 0; i < 8; i++) ss += red_s[i];
        bc[1] = ss;
    }
    __syncthreads();
    float alpha = e / bc[1];
    __syncthreads();   // sc reads (scores) done above; safe to overwrite now
    if (tid < NPIX) {
        sc[tid] = alpha;
        out_alphas[(size_t)b*TT*NPIX + (size_t)t*NPIX + tid] = alpha;
    }
    __syncthreads();

    // ctx[d] = gate[d] * sum_p alpha[p] * enc[b,p,d]
    const float* encb = d_enc_s + (size_t)b*NPIX*512;
    for (int d = tid; d < 512; d += 256) {
        float s2 = 0.f;
        #pragma unroll 4
        for (int p = 0; p < NPIX; p++) s2 += sc[p] * encb[p*512 + d];
        d_ctx[b*512 + d] = s2 * sh_g[d];
    }
}

// ---------------- LSTM gate GEMM: gates = [emb|ctx]@Wih^T + h@Whh^T + b ------
__global__ __launch_bounds__(256) void lstm_gemm_kernel(int t,
        const float* __restrict__ emb, const float* __restrict__ Wih,
        const float* __restrict__ Whh, const float* __restrict__ bih,
        const float* __restrict__ bhh) {
    __shared__ float sA[32][64];
    __shared__ float sW[32][64];
    __shared__ int   stok[64];
    int tid = threadIdx.x;
    if (tid < 64) stok[tid] = d_caps_s[tid*ML + t];
    __syncthreads();
    int tx = tid & 15, ty = tid >> 4;
    int n0 = blockIdx.x * 64;
    float acc[4][4] = {};
    for (int k0 = 0; k0 < 1536; k0 += 32) {
        #pragma unroll
        for (int u = 0; u < 2; u++) {
            int f4i = tid + u*256;
            int m  = f4i >> 3;
            int kk = (f4i & 7) << 2;
            int k  = k0 + kk;
            float4 a;
            if (k < 512)       a = *(const float4*)&emb[(size_t)stok[m]*512 + k];
            else if (k < 1024) a = *(const float4*)&d_ctx[m*512 + (k - 512)];
            else               a = *(const float4*)&d_h[m*512 + (k - 1024)];
            sA[kk][m] = a.x; sA[kk+1][m] = a.y; sA[kk+2][m] = a.z; sA[kk+3][m] = a.w;
            float4 w;
            if (k < 1024) w = *(const float4*)&Wih[(size_t)(n0+m)*1024 + k];
            else          w = *(const float4*)&Whh[(size_t)(n0+m)*512 + (k - 1024)];
            sW[kk][m] = w.x; sW[kk+1][m] = w.y; sW[kk+2][m] = w.z; sW[kk+3][m] = w.w;
        }
        __syncthreads();
        #pragma unroll
        for (int k = 0; k < 32; k++) {
            float4 a = *(const float4*)&sA[k][ty*4];
            float4 w = *(const float4*)&sW[k][tx*4];
            float av[4] = {a.x, a.y, a.z, a.w};
            float wv[4] = {w.x, w.y, w.z, w.w};
            #pragma unroll
            for (int i = 0; i < 4; i++)
                #pragma unroll
                for (int j = 0; j < 4; j++)
                    acc[i][j] += av[i] * wv[j];
        }
        __syncthreads();
    }
    #pragma unroll
    for (int i = 0; i < 4; i++) {
        int m = ty*4 + i;
        #pragma unroll
        for (int j = 0; j < 4; j++) {
            int n = n0 + tx*4 + j;
            d_gates[m*2048 + n] = acc[i][j] + bih[n] + bhh[n];
        }
    }
}

// ---------------- LSTM pointwise -----------------------------------------------
__global__ __launch_bounds__(256) void lstm_apply_kernel() {
    int idx = blockIdx.x*256 + threadIdx.x;  // BSZ*DD = 32768
    int b = idx >> 9;
    int j = idx & 511;
    const float* g = d_gates + b*2048;
    float ig = sigmoidf_(g[j]);
    float fg = sigmoidf_(g[512 + j]);
    float gg = tanhf(g[1024 + j]);
    float og = sigmoidf_(g[1536 + j]);
    float c  = fg * d_c[idx] + ig * gg;
    float h  = og * tanhf(c);
    d_c[idx] = c;
    d_h[idx] = h;
}

// ---------------- vocab projection: preds = h @ Wfc^T + bfc (masked) ----------
__global__ __launch_bounds__(128) void preds_kernel(int t,
        const float* __restrict__ Wfc, const float* __restrict__ bfc,
        float* __restrict__ out_pred) {
    int nact = d_nact[t];
    int m0 = blockIdx.y * 16;
    if (m0 >= nact) return;       // prefix-sorted activity: whole block inactive
    __shared__ float sA[32][16];
    __shared__ float sW[32][128];
    int tid = threadIdx.x;        // 128
    int tx = tid & 31, ty = tid >> 5;
    int n0 = blockIdx.x * 128;
    float acc[4][4] = {};
    for (int k0 = 0; k0 < 512; k0 += 32) {
        {   // A tile: 16x32 = 128 float4, one per thread
            int m  = tid >> 3;
            int kk = (tid & 7) << 2;
            float4 a = *(const float4*)&d_h[(m0+m)*512 + k0 + kk];
            sA[kk][m] = a.x; sA[kk+1][m] = a.y; sA[kk+2][m] = a.z; sA[kk+3][m] = a.w;
        }
        #pragma unroll
        for (int u = 0; u < 8; u++) {  // W tile: 128x32 = 1024 float4
            int f4i = tid + u*128;
            int n  = f4i >> 3;
            int kk = (f4i & 7) << 2;
            float4 w = *(const float4*)&Wfc[(size_t)(n0+n)*512 + k0 + kk];
            sW[kk][n] = w.x; sW[kk+1][n] = w.y; sW[kk+2][n] = w.z; sW[kk+3][n] = w.w;
        }
        __syncthreads();
        #pragma unroll
        for (int k = 0; k < 32; k++) {
            float4 a = *(const float4*)&sA[k][ty*4];
            float4 w = *(const float4*)&sW[k][tx*4];
            float av[4] = {a.x, a.y, a.z, a.w};
            float wv[4] = {w.x, w.y, w.z, w.w};
            #pragma unroll
            for (int i = 0; i < 4; i++)
                #pragma unroll
                for (int j = 0; j < 4; j++)
                    acc[i][j] += av[i] * wv[j];
        }
        __syncthreads();
    }
    int n = n0 + tx*4;
    float4 bb = *(const float4*)&bfc[n];
    #pragma unroll
    for (int i = 0; i < 4; i++) {
        int m = m0 + ty*4 + i;
        if (m >= nact) continue;
        float4 o;
        o.x = acc[i][0] + bb.x;
        o.y = acc[i][1] + bb.y;
        o.z = acc[i][2] + bb.z;
        o.w = acc[i][3] + bb.w;
        *(float4*)&out_pred[(size_t)m*(TT*(size_t)VV) + (size_t)t*VV + n] = o;
    }
}

// ---------------- launch ------------------------------------------------------
extern "C" void kernel_launch(void* const* d_in, const int* in_sizes, int n_in,
                              void* d_out, int out_size) {
    const float* encoder_out = (const float*)d_in[0];
    const int*   caps        = (const int*)  d_in[1];
    const int*   cap_len     = (const int*)  d_in[2];
    const float* W_enc_attn  = (const float*)d_in[3];
    const float* b_enc_attn  = (const float*)d_in[4];
    const float* W_dec_attn  = (const float*)d_in[5];
    const float* b_dec_attn  = (const float*)d_in[6];
    const float* w_full_attn = (const float*)d_in[7];
    const float* b_full_attn = (const float*)d_in[8];
    const float* emb_table   = (const float*)d_in[9];
    const float* W_ih        = (const float*)d_in[10];
    const float* W_hh        = (const float*)d_in[11];
    const float* b_ih        = (const float*)d_in[12];
    const float* b_hh        = (const float*)d_in[13];
    const float* W_init_h    = (const float*)d_in[14];
    const float* b_init_h    = (const float*)d_in[15];
    const float* W_init_c    = (const float*)d_in[16];
    const float* b_init_c    = (const float*)d_in[17];
    const float* W_f_beta    = (const float*)d_in[18];
    const float* b_f_beta    = (const float*)d_in[19];
    const float* W_fc        = (const float*)d_in[20];
    const float* b_fc        = (const float*)d_in[21];

    float* out = (float*)d_out;
    // output layout: predictions | caps | dec_len | alphas | order (all as f32)
    const size_t OFF_PRED   = 0;
    const size_t OFF_CAPS   = OFF_PRED + (size_t)BSZ*TT*VV;     // 102,400,000
    const size_t OFF_DECLEN = OFF_CAPS + (size_t)BSZ*ML;        // +3264
    const size_t OFF_ALPHA  = OFF_DECLEN + BSZ;                 // +64
    const size_t OFF_ORDER  = OFF_ALPHA + (size_t)BSZ*TT*NPIX;  // +627,200
    float* out_pred   = out + OFF_PRED;
    float* out_caps   = out + OFF_CAPS;
    float* out_declen = out + OFF_DECLEN;
    float* out_alphas = out + OFF_ALPHA;
    float* out_order  = out + OFF_ORDER;

    // zero everything (masked preds/alphas must be 0; buffer is poisoned)
    cudaMemsetAsync(d_out, 0, (size_t)out_size * sizeof(float));

    sort_kernel<<<1, 64>>>(cap_len, caps, out_caps, out_declen, out_order);
    reorder_mean_kernel<<<BSZ, 256>>>(encoder_out);

    // ea = enc_s @ W_enc_attn^T + b   (M=12544, N=512, K=512)
    gemm64_kernel<<<dim3(8, 196), 256>>>(0, W_enc_attn, b_enc_attn, 512, 512);
    // h0 / c0
    gemm64_kernel<<<dim3(8, 1), 256>>>(1, W_init_h, b_init_h, 512, 512);
    gemm64_kernel<<<dim3(8, 1), 256>>>(2, W_init_c, b_init_c, 512, 512);

    for (int t = 0; t < TT; t++) {
        attn_kernel<<<BSZ, 256>>>(t, W_dec_attn, b_dec_attn, w_full_attn,
                                  b_full_attn, W_f_beta, b_f_beta, out_alphas);
        lstm_gemm_kernel<<<32, 256>>>(t, emb_table, W_ih, W_hh, b_ih, b_hh);
        lstm_apply_kernel<<<(BSZ*DD)/256, 256>>>();
        preds_kernel<<<dim3(VV/128, 4), 128>>>(t, W_fc, b_fc, out_pred);
    }
}

// round 2
// speedup vs baseline: 1.7752x; 1.7752x over previous
#include <cuda_runtime.h>
#include <math.h>

#define BSZ 64
#define NPIX 196
#define ENCD 512
#define DD 512
#define VV 32000
#define TT 50
#define ML 51

// ---------------- scratch (static device globals; no runtime alloc) ----------
__device__ float d_enc_s[BSZ*NPIX*ENCD];   // sorted encoder features
__device__ float d_ea[BSZ*NPIX*ENCD];      // enc @ W_enc_attn^T + b
__device__ float d_mean[BSZ*ENCD];
__device__ float d_h[BSZ*DD];
__device__ float d_c[BSZ*DD];
__device__ float d_ctx[BSZ*ENCD];
__device__ float d_da[BSZ*DD];             // h @ W_dec_attn^T + b (precomputed per step)
__device__ float d_gate[BSZ*ENCD];         // sigmoid(h @ W_f_beta^T + b)
__device__ float d_gates_p[4*BSZ*4*DD];    // split-K partials for LSTM gates
__device__ int   d_order[BSZ];
__device__ int   d_declen[BSZ];
__device__ int   d_caps_s[BSZ*ML];
__device__ int   d_nact[TT];

// ---------------- helpers ----------------------------------------------------
__device__ __forceinline__ float warp_sum(float v) {
    #pragma unroll
    for (int o = 16; o > 0; o >>= 1) v += __shfl_down_sync(0xffffffffu, v, o);
    return v;
}
__device__ __forceinline__ float warp_max(float v) {
    #pragma unroll
    for (int o = 16; o > 0; o >>= 1) v = fmaxf(v, __shfl_down_sync(0xffffffffu, v, o));
    return v;
}
__device__ __forceinline__ float sigmoidf_(float x) { return 1.0f / (1.0f + __expf(-x)); }

// ---------------- sort (stable, descending cap_len) ---------------------------
__global__ void sort_kernel(const int* __restrict__ cap_len,
                            const int* __restrict__ caps,
                            float* __restrict__ out_caps,
                            float* __restrict__ out_declen,
                            float* __restrict__ out_order) {
    int i = threadIdx.x;  // 64 threads
    int cl = cap_len[i];
    int r = 0;
    for (int j = 0; j < BSZ; j++) {
        int cj = cap_len[j];
        if (cj > cl || (cj == cl && j < i)) r++;
    }
    d_order[r]  = i;
    d_declen[r] = cl - 1;
    __syncthreads();
    out_order[i]  = (float)d_order[i];
    out_declen[i] = (float)d_declen[i];
    int src = d_order[i];
    for (int tt = 0; tt < ML; tt++) {
        int tok = caps[src*ML + tt];
        d_caps_s[i*ML + tt] = tok;
        out_caps[i*ML + tt] = (float)tok;
    }
    if (i < TT) {
        int cnt = 0;
        for (int j = 0; j < BSZ; j++) if (d_declen[j] > i) cnt++;
        d_nact[i] = cnt;
    }
}

// ---------------- reorder encoder + per-batch pixel mean ----------------------
__global__ __launch_bounds__(256) void reorder_mean_kernel(const float* __restrict__ enc) {
    int b = blockIdx.x;
    int tid = threadIdx.x;  // 256
    int src = d_order[b];
    const float* Ein = enc + (size_t)src*NPIX*ENCD;
    float* Eo = d_enc_s + (size_t)b*NPIX*ENCD;
    float s0 = 0.f, s1 = 0.f;
    for (int p = 0; p < NPIX; p++) {
        float v0 = Ein[p*ENCD + tid];
        float v1 = Ein[p*ENCD + tid + 256];
        Eo[p*ENCD + tid]       = v0;
        Eo[p*ENCD + tid + 256] = v1;
        s0 += v0; s1 += v1;
    }
    d_mean[b*ENCD + tid]       = s0 * (1.0f/NPIX);
    d_mean[b*ENCD + tid + 256] = s1 * (1.0f/NPIX);
}

// ---------------- generic 64x64 tiled GEMM: C = A @ W^T + bias ---------------
// sel: 0 -> A=d_enc_s, C=d_ea ; 1 -> A=d_mean, C=d_h ; 2 -> A=d_mean, C=d_c
__global__ __launch_bounds__(256) void gemm64_kernel(int sel,
        const float* __restrict__ Wmat, const float* __restrict__ bias,
        int K, int N) {
    const float* Amat = (sel == 0) ? d_enc_s : d_mean;
    float*       Cmat = (sel == 0) ? d_ea : ((sel == 1) ? d_h : d_c);
    __shared__ float sA[32][64];
    __shared__ float sW[32][64];
    int tid = threadIdx.x;
    int tx = tid & 15, ty = tid >> 4;
    int m0 = blockIdx.y * 64;
    int n0 = blockIdx.x * 64;
    float acc[4][4] = {};
    for (int k0 = 0; k0 < K; k0 += 32) {
        #pragma unroll
        for (int u = 0; u < 2; u++) {
            int f4i = tid + u*256;
            int m  = f4i >> 3;
            int kk = (f4i & 7) << 2;
            float4 a = *(const float4*)&Amat[(size_t)(m0+m)*K + k0 + kk];
            sA[kk][m] = a.x; sA[kk+1][m] = a.y; sA[kk+2][m] = a.z; sA[kk+3][m] = a.w;
            float4 w = *(const float4*)&Wmat[(size_t)(n0+m)*K + k0 + kk];
            sW[kk][m] = w.x; sW[kk+1][m] = w.y; sW[kk+2][m] = w.z; sW[kk+3][m] = w.w;
        }
        __syncthreads();
        #pragma unroll
        for (int k = 0; k < 32; k++) {
            float4 a = *(const float4*)&sA[k][ty*4];
            float4 w = *(const float4*)&sW[k][tx*4];
            float av[4] = {a.x, a.y, a.z, a.w};
            float wv[4] = {w.x, w.y, w.z, w.w};
            #pragma unroll
            for (int i = 0; i < 4; i++)
                #pragma unroll
                for (int j = 0; j < 4; j++)
                    acc[i][j] += av[i] * wv[j];
        }
        __syncthreads();
    }
    #pragma unroll
    for (int i = 0; i < 4; i++) {
        int m = m0 + ty*4 + i;
        #pragma unroll
        for (int j = 0; j < 4; j++) {
            int n = n0 + tx*4 + j;
            Cmat[(size_t)m*N + n] = acc[i][j] + bias[n];
        }
    }
}

// ---------------- da / gate GEMM: [da|gate] = h @ [Wd;Wg]^T ------------------
// n in [0,512): da = h@Wd^T + bd ; n in [512,1024): gate = sigmoid(h@Wg^T + bg)
__global__ __launch_bounds__(256) void dagate_kernel(
        const float* __restrict__ Wd, const float* __restrict__ bd,
        const float* __restrict__ Wg, const float* __restrict__ bg) {
    __shared__ float sA[32][64];
    __shared__ float sW[32][64];
    int tid = threadIdx.x;
    int tx = tid & 15, ty = tid >> 4;
    int n0 = blockIdx.x * 64;                 // 0..960, never straddles 512
    const float* Wmat = (n0 < 512) ? (Wd + (size_t)n0*512) : (Wg + (size_t)(n0-512)*512);
    float acc[4][4] = {};
    for (int k0 = 0; k0 < 512; k0 += 32) {
        #pragma unroll
        for (int u = 0; u < 2; u++) {
            int f4i = tid + u*256;
            int m  = f4i >> 3;
            int kk = (f4i & 7) << 2;
            float4 a = *(const float4*)&d_h[(size_t)m*512 + k0 + kk];
            sA[kk][m] = a.x; sA[kk+1][m] = a.y; sA[kk+2][m] = a.z; sA[kk+3][m] = a.w;
            float4 w = *(const float4*)&Wmat[(size_t)m*512 + k0 + kk];
            sW[kk][m] = w.x; sW[kk+1][m] = w.y; sW[kk+2][m] = w.z; sW[kk+3][m] = w.w;
        }
        __syncthreads();
        #pragma unroll
        for (int k = 0; k < 32; k++) {
            float4 a = *(const float4*)&sA[k][ty*4];
            float4 w = *(const float4*)&sW[k][tx*4];
            float av[4] = {a.x, a.y, a.z, a.w};
            float wv[4] = {w.x, w.y, w.z, w.w};
            #pragma unroll
            for (int i = 0; i < 4; i++)
                #pragma unroll
                for (int j = 0; j < 4; j++)
                    acc[i][j] += av[i] * wv[j];
        }
        __syncthreads();
    }
    #pragma unroll
    for (int i = 0; i < 4; i++) {
        int m = ty*4 + i;
        #pragma unroll
        for (int j = 0; j < 4; j++) {
            int n = n0 + tx*4 + j;
            if (n < 512) d_da[m*512 + n] = acc[i][j] + bd[n];
            else         d_gate[m*512 + (n-512)] = sigmoidf_(acc[i][j] + bg[n-512]);
        }
    }
}

// ---------------- attention step (scores, softmax, ctx) -----------------------
__global__ __launch_bounds__(256) void attn_kernel(int t,
        const float* __restrict__ wf, const float* __restrict__ bf_scalar,
        float* __restrict__ out_alphas) {
    int b = blockIdx.x;
    if (t >= d_declen[b]) return;   // inactive: outputs already zero, h/c unused
    int tid  = threadIdx.x;
    int lane = tid & 31, warp = tid >> 5;   // 8 warps

    __shared__ float4 s_da[128], s_wf[128];
    __shared__ float sc[NPIX];
    __shared__ float red_m[8], red_s[8], bc[2];

    if (tid < 128) {
        s_da[tid] = ((const float4*)d_da)[b*128 + tid];
        s_wf[tid] = ((const float4*)wf)[tid];
    }
    __syncthreads();

    // scores[p] = relu(ea[b,p,:] + da) . wf + b_full
    const float4* ea4 = ((const float4*)d_ea) + (size_t)b*NPIX*128;
    float bfull = bf_scalar[0];
    for (int p = warp; p < NPIX; p += 8) {
        float s = 0.f;
        #pragma unroll
        for (int j = 0; j < 4; j++) {
            int k4 = lane + j*32;
            float4 e = ea4[p*128 + k4];
            float4 da = s_da[k4];
            float4 w  = s_wf[k4];
            s += fmaxf(e.x + da.x, 0.f) * w.x;
            s += fmaxf(e.y + da.y, 0.f) * w.y;
            s += fmaxf(e.z + da.z, 0.f) * w.z;
            s += fmaxf(e.w + da.w, 0.f) * w.w;
        }
        s = warp_sum(s);
        if (lane == 0) sc[p] = s + bfull;
    }
    __syncthreads();

    // softmax over 196
    float v = (tid < NPIX) ? sc[tid] : -1e30f;
    float wm = warp_max(v);
    if (lane == 0) red_m[warp] = wm;
    __syncthreads();
    if (tid == 0) {
        float mm = red_m[0];
        #pragma unroll
        for (int i = 1; i < 8; i++) mm = fmaxf(mm, red_m[i]);
        bc[0] = mm;
    }
    __syncthreads();
    float gmax = bc[0];
    float e = (tid < NPIX) ? __expf(v - gmax) : 0.f;
    float ws = warp_sum(e);
    if (lane == 0) red_s[warp] = ws;
    __syncthreads();
    if (tid == 0) {
        float ss = 0.f;
        #pragma unroll
        for (int i = 0; i < 8; i++) ss += red_s[i];
        bc[1] = ss;
    }
    __syncthreads();
    float alpha = e / bc[1];
    __syncthreads();
    if (tid < NPIX) {
        sc[tid] = alpha;
        out_alphas[(size_t)b*TT*NPIX + (size_t)t*NPIX + tid] = alpha;
    }
    __syncthreads();

    // ctx[d] = gate[d] * sum_p alpha[p] * enc[b,p,d]
    const float* encb = d_enc_s + (size_t)b*NPIX*512;
    for (int d = tid; d < 512; d += 256) {
        float s2 = 0.f;
        #pragma unroll 4
        for (int p = 0; p < NPIX; p++) s2 += sc[p] * encb[p*512 + d];
        d_ctx[b*512 + d] = s2 * d_gate[b*512 + d];
    }
}

// ---------------- LSTM gate GEMM (split-K x4): partials ----------------------
__global__ __launch_bounds__(256) void lstm_gemm_kernel(int t,
        const float* __restrict__ emb, const float* __restrict__ Wih,
        const float* __restrict__ Whh) {
    __shared__ float sA[32][64];
    __shared__ float sW[32][64];
    __shared__ int   stok[64];
    int tid = threadIdx.x;
    if (tid < 64) stok[tid] = d_caps_s[tid*ML + t];
    __syncthreads();
    int tx = tid & 15, ty = tid >> 4;
    int n0 = blockIdx.x * 64;
    int kbase = blockIdx.y * 384;    // 4 splits of 384 (K=1536)
    float acc[4][4] = {};
    for (int k0 = kbase; k0 < kbase + 384; k0 += 32) {
        #pragma unroll
        for (int u = 0; u < 2; u++) {
            int f4i = tid + u*256;
            int m  = f4i >> 3;
            int kk = (f4i & 7) << 2;
            int k  = k0 + kk;
            float4 a;
            if (k < 512)       a = *(const float4*)&emb[(size_t)stok[m]*512 + k];
            else if (k < 1024) a = *(const float4*)&d_ctx[m*512 + (k - 512)];
            else               a = *(const float4*)&d_h[m*512 + (k - 1024)];
            sA[kk][m] = a.x; sA[kk+1][m] = a.y; sA[kk+2][m] = a.z; sA[kk+3][m] = a.w;
            float4 w;
            if (k < 1024) w = *(const float4*)&Wih[(size_t)(n0+m)*1024 + k];
            else          w = *(const float4*)&Whh[(size_t)(n0+m)*512 + (k - 1024)];
            sW[kk][m] = w.x; sW[kk+1][m] = w.y; sW[kk+2][m] = w.z; sW[kk+3][m] = w.w;
        }
        __syncthreads();
        #pragma unroll
        for (int k = 0; k < 32; k++) {
            float4 a = *(const float4*)&sA[k][ty*4];
            float4 w = *(const float4*)&sW[k][tx*4];
            float av[4] = {a.x, a.y, a.z, a.w};
            float wv[4] = {w.x, w.y, w.z, w.w};
            #pragma unroll
            for (int i = 0; i < 4; i++)
                #pragma unroll
                for (int j = 0; j < 4; j++)
                    acc[i][j] += av[i] * wv[j];
        }
        __syncthreads();
    }
    float* gp = d_gates_p + (size_t)blockIdx.y * (BSZ*2048);
    #pragma unroll
    for (int i = 0; i < 4; i++) {
        int m = ty*4 + i;
        #pragma unroll
        for (int j = 0; j < 4; j++) {
            int n = n0 + tx*4 + j;
            gp[m*2048 + n] = acc[i][j];
        }
    }
}

// ---------------- LSTM pointwise (reduce split-K partials) --------------------
__global__ __launch_bounds__(256) void lstm_apply_kernel(
        const float* __restrict__ bih, const float* __restrict__ bhh) {
    int idx = blockIdx.x*256 + threadIdx.x;  // BSZ*DD = 32768
    int b = idx >> 9;
    int j = idx & 511;
    float gi = 0.f, gf = 0.f, gg = 0.f, go = 0.f;
    #pragma unroll
    for (int s = 0; s < 4; s++) {
        const float* g = d_gates_p + (size_t)s*(BSZ*2048) + b*2048;
        gi += g[j];
        gf += g[512 + j];
        gg += g[1024 + j];
        go += g[1536 + j];
    }
    gi += bih[j]        + bhh[j];
    gf += bih[512 + j]  + bhh[512 + j];
    gg += bih[1024 + j] + bhh[1024 + j];
    go += bih[1536 + j] + bhh[1536 + j];
    float ig = sigmoidf_(gi);
    float fg = sigmoidf_(gf);
    float g2 = tanhf(gg);
    float og = sigmoidf_(go);
    float c  = fg * d_c[idx] + ig * g2;
    float h  = og * tanhf(c);
    d_c[idx] = c;
    d_h[idx] = h;
}

// ---------------- vocab projection: preds = h @ Wfc^T + bfc (masked) ----------
// tile 16(M) x 256(N), 128 threads, per-thread 4x8, k-vectorized (float4)
__global__ __launch_bounds__(128) void preds_kernel(int t,
        const float* __restrict__ Wfc, const float* __restrict__ bfc,
        float* __restrict__ out_pred) {
    int nact = d_nact[t];
    int m0 = blockIdx.y * 16;
    if (m0 >= nact) return;       // prefix-sorted activity: whole block inactive
    __shared__ float4 sA4[16][8];
    __shared__ float4 sW4[256][9];   // pad to 9 -> conflict-free loads
    int tid = threadIdx.x;           // 128
    int tx = tid & 31, ty = tid >> 5;
    int n0 = blockIdx.x * 256;
    const float4* h4 = (const float4*)d_h;
    const float4* W4 = (const float4*)Wfc;
    float acc[4][8] = {};
    for (int k0 = 0; k0 < 128; k0 += 8) {   // k in float4 units (512/4=128)
        {
            int m  = tid >> 3;
            int kv = tid & 7;
            sA4[m][kv] = h4[(size_t)(m0+m)*128 + k0 + kv];
        }
        #pragma unroll
        for (int u = 0; u < 16; u++) {
            int f4i = tid + u*128;
            int n  = f4i >> 3;
            int kv = f4i & 7;
            sW4[n][kv] = W4[(size_t)(n0+n)*128 + k0 + kv];
        }
        __syncthreads();
        #pragma unroll
        for (int kv = 0; kv < 8; kv++) {
            float4 a[4];
            #pragma unroll
            for (int i = 0; i < 4; i++) a[i] = sA4[ty*4 + i][kv];
            #pragma unroll
            for (int j = 0; j < 8; j++) {
                float4 w = sW4[tx + 32*j][kv];
                #pragma unroll
                for (int i = 0; i < 4; i++) {
                    acc[i][j] += a[i].x*w.x;
                    acc[i][j] += a[i].y*w.y;
                    acc[i][j] += a[i].z*w.z;
                    acc[i][j] += a[i].w*w.w;
                }
            }
        }
        __syncthreads();
    }
    #pragma unroll
    for (int j = 0; j < 8; j++) {
        int n = n0 + tx + 32*j;
        float bb = bfc[n];
        #pragma unroll
        for (int i = 0; i < 4; i++) {
            int m = m0 + ty*4 + i;
            if (m < nact)
                out_pred[(size_t)m*(TT*(size_t)VV) + (size_t)t*VV + n] = acc[i][j] + bb;
        }
    }
}

// ---------------- launch ------------------------------------------------------
extern "C" void kernel_launch(void* const* d_in, const int* in_sizes, int n_in,
                              void* d_out, int out_size) {
    const float* encoder_out = (const float*)d_in[0];
    const int*   caps        = (const int*)  d_in[1];
    const int*   cap_len     = (const int*)  d_in[2];
    const float* W_enc_attn  = (const float*)d_in[3];
    const float* b_enc_attn  = (const float*)d_in[4];
    const float* W_dec_attn  = (const float*)d_in[5];
    const float* b_dec_attn  = (const float*)d_in[6];
    const float* w_full_attn = (const float*)d_in[7];
    const float* b_full_attn = (const float*)d_in[8];
    const float* emb_table   = (const float*)d_in[9];
    const float* W_ih        = (const float*)d_in[10];
    const float* W_hh        = (const float*)d_in[11];
    const float* b_ih        = (const float*)d_in[12];
    const float* b_hh        = (const float*)d_in[13];
    const float* W_init_h    = (const float*)d_in[14];
    const float* b_init_h    = (const float*)d_in[15];
    const float* W_init_c    = (const float*)d_in[16];
    const float* b_init_c    = (const float*)d_in[17];
    const float* W_f_beta    = (const float*)d_in[18];
    const float* b_f_beta    = (const float*)d_in[19];
    const float* W_fc        = (const float*)d_in[20];
    const float* b_fc        = (const float*)d_in[21];

    float* out = (float*)d_out;
    // output layout: predictions | caps | dec_len | alphas | order (all as f32)
    const size_t OFF_PRED   = 0;
    const size_t OFF_CAPS   = OFF_PRED + (size_t)BSZ*TT*VV;     // 102,400,000
    const size_t OFF_DECLEN = OFF_CAPS + (size_t)BSZ*ML;        // +3264
    const size_t OFF_ALPHA  = OFF_DECLEN + BSZ;                 // +64
    const size_t OFF_ORDER  = OFF_ALPHA + (size_t)BSZ*TT*NPIX;  // +627,200
    float* out_pred   = out + OFF_PRED;
    float* out_caps   = out + OFF_CAPS;
    float* out_declen = out + OFF_DECLEN;
    float* out_alphas = out + OFF_ALPHA;
    float* out_order  = out + OFF_ORDER;

    // zero everything (masked preds/alphas must be 0; buffer is poisoned)
    cudaMemsetAsync(d_out, 0, (size_t)out_size * sizeof(float));

    sort_kernel<<<1, 64>>>(cap_len, caps, out_caps, out_declen, out_order);
    reorder_mean_kernel<<<BSZ, 256>>>(encoder_out);

    // ea = enc_s @ W_enc_attn^T + b   (M=12544, N=512, K=512)
    gemm64_kernel<<<dim3(8, 196), 256>>>(0, W_enc_attn, b_enc_attn, 512, 512);
    // h0 / c0
    gemm64_kernel<<<dim3(8, 1), 256>>>(1, W_init_h, b_init_h, 512, 512);
    gemm64_kernel<<<dim3(8, 1), 256>>>(2, W_init_c, b_init_c, 512, 512);
    // da/gate for step 0 (from h0)
    dagate_kernel<<<16, 256>>>(W_dec_attn, b_dec_attn, W_f_beta, b_f_beta);

    for (int t = 0; t < TT; t++) {
        attn_kernel<<<BSZ, 256>>>(t, w_full_attn, b_full_attn, out_alphas);
        lstm_gemm_kernel<<<dim3(32, 4), 256>>>(t, emb_table, W_ih, W_hh);
        lstm_apply_kernel<<<(BSZ*DD)/256, 256>>>(b_ih, b_hh);
        dagate_kernel<<<16, 256>>>(W_dec_attn, b_dec_attn, W_f_beta, b_f_beta);
        preds_kernel<<<dim3(VV/256, 4), 128>>>(t, W_fc, b_fc, out_pred);
    }
}

// round 3
// speedup vs baseline: 1.8674x; 1.0519x over previous
#include <cuda_runtime.h>
#include <math.h>
#include <stdint.h>

#define BSZ 64
#define NPIX 196
#define ENCD 512
#define DD 512
#define VV 32000
#define TT 50
#define ML 51

// ---------------- scratch (static device globals; no runtime alloc) ----------
__device__ float d_enc_s[BSZ*NPIX*ENCD];   // sorted encoder features
__device__ float d_ea[BSZ*NPIX*ENCD];      // enc @ W_enc_attn^T + b
__device__ float d_mean[BSZ*ENCD];
__device__ float d_h[BSZ*DD];
__device__ float d_c[BSZ*DD];
__device__ float d_ctx[BSZ*ENCD];
__device__ float d_da[BSZ*DD];             // h @ W_dec_attn^T + b
__device__ float d_gate[BSZ*ENCD];         // sigmoid(h @ W_f_beta^T + b)
__device__ float d_gates_p[4*BSZ*4*DD];    // split-K partials for LSTM gates
__device__ uint4 d_wfh[(size_t)VV*128];    // W_fc tf32 hi (65MB)
__device__ uint4 d_wfl[(size_t)VV*128];    // W_fc tf32 lo (65MB)
__device__ int   d_order[BSZ];
__device__ int   d_declen[BSZ];
__device__ int   d_caps_s[BSZ*ML];
__device__ int   d_nact[TT];

// ---------------- helpers ----------------------------------------------------
__device__ __forceinline__ float warp_sum(float v) {
    #pragma unroll
    for (int o = 16; o > 0; o >>= 1) v += __shfl_down_sync(0xffffffffu, v, o);
    return v;
}
__device__ __forceinline__ float warp_max(float v) {
    #pragma unroll
    for (int o = 16; o > 0; o >>= 1) v = fmaxf(v, __shfl_down_sync(0xffffffffu, v, o));
    return v;
}
__device__ __forceinline__ float sigmoidf_(float x) { return 1.0f / (1.0f + __expf(-x)); }
__device__ __forceinline__ uint32_t f2tf32(float x) {
    uint32_t r; asm("cvt.rna.tf32.f32 %0, %1;" : "=r"(r) : "f"(x)); return r;
}
__device__ __forceinline__ void mma_tf32(float c[4], uint32_t a0, uint32_t a1,
                                         uint32_t a2, uint32_t a3,
                                         uint32_t b0, uint32_t b1) {
    asm volatile(
        "mma.sync.aligned.m16n8k8.row.col.f32.tf32.tf32.f32 "
        "{%0,%1,%2,%3}, {%4,%5,%6,%7}, {%8,%9}, {%0,%1,%2,%3};\n"
        : "+f"(c[0]), "+f"(c[1]), "+f"(c[2]), "+f"(c[3])
        : "r"(a0), "r"(a1), "r"(a2), "r"(a3), "r"(b0), "r"(b1));
}

// ---------------- one-time: split W_fc into tf32 hi/lo -----------------------
__global__ __launch_bounds__(256) void convert_wfc_kernel(const float4* __restrict__ W) {
    size_t i = (size_t)blockIdx.x*256 + threadIdx.x;   // over 32000*128 float4
    float4 v = W[i];
    uint4 h, l;
    h.x = f2tf32(v.x); l.x = f2tf32(v.x - __uint_as_float(h.x));
    h.y = f2tf32(v.y); l.y = f2tf32(v.y - __uint_as_float(h.y));
    h.z = f2tf32(v.z); l.z = f2tf32(v.z - __uint_as_float(h.z));
    h.w = f2tf32(v.w); l.w = f2tf32(v.w - __uint_as_float(h.w));
    d_wfh[i] = h; d_wfl[i] = l;
}

// ---------------- sort (stable, descending cap_len) ---------------------------
__global__ void sort_kernel(const int* __restrict__ cap_len,
                            const int* __restrict__ caps,
                            float* __restrict__ out_caps,
                            float* __restrict__ out_declen,
                            float* __restrict__ out_order) {
    int i = threadIdx.x;  // 64 threads
    int cl = cap_len[i];
    int r = 0;
    for (int j = 0; j < BSZ; j++) {
        int cj = cap_len[j];
        if (cj > cl || (cj == cl && j < i)) r++;
    }
    d_order[r]  = i;
    d_declen[r] = cl - 1;
    __syncthreads();
    out_order[i]  = (float)d_order[i];
    out_declen[i] = (float)d_declen[i];
    int src = d_order[i];
    for (int tt = 0; tt < ML; tt++) {
        int tok = caps[src*ML + tt];
        d_caps_s[i*ML + tt] = tok;
        out_caps[i*ML + tt] = (float)tok;
    }
    if (i < TT) {
        int cnt = 0;
        for (int j = 0; j < BSZ; j++) if (d_declen[j] > i) cnt++;
        d_nact[i] = cnt;
    }
}

// ---------------- reorder encoder + per-batch pixel mean ----------------------
__global__ __launch_bounds__(256) void reorder_mean_kernel(const float* __restrict__ enc) {
    int b = blockIdx.x;
    int tid = threadIdx.x;  // 256
    int src = d_order[b];
    const float* Ein = enc + (size_t)src*NPIX*ENCD;
    float* Eo = d_enc_s + (size_t)b*NPIX*ENCD;
    float s0 = 0.f, s1 = 0.f;
    for (int p = 0; p < NPIX; p++) {
        float v0 = Ein[p*ENCD + tid];
        float v1 = Ein[p*ENCD + tid + 256];
        Eo[p*ENCD + tid]       = v0;
        Eo[p*ENCD + tid + 256] = v1;
        s0 += v0; s1 += v1;
    }
    d_mean[b*ENCD + tid]       = s0 * (1.0f/NPIX);
    d_mean[b*ENCD + tid + 256] = s1 * (1.0f/NPIX);
}

// ---------------- generic 64x64 tiled GEMM: C = A @ W^T + bias ---------------
__global__ __launch_bounds__(256) void gemm64_kernel(int sel,
        const float* __restrict__ Wmat, const float* __restrict__ bias,
        int K, int N) {
    const float* Amat = (sel == 0) ? d_enc_s : d_mean;
    float*       Cmat = (sel == 0) ? d_ea : ((sel == 1) ? d_h : d_c);
    __shared__ float sA[32][64];
    __shared__ float sW[32][64];
    int tid = threadIdx.x;
    int tx = tid & 15, ty = tid >> 4;
    int m0 = blockIdx.y * 64;
    int n0 = blockIdx.x * 64;
    float acc[4][4] = {};
    for (int k0 = 0; k0 < K; k0 += 32) {
        #pragma unroll
        for (int u = 0; u < 2; u++) {
            int f4i = tid + u*256;
            int m  = f4i >> 3;
            int kk = (f4i & 7) << 2;
            float4 a = *(const float4*)&Amat[(size_t)(m0+m)*K + k0 + kk];
            sA[kk][m] = a.x; sA[kk+1][m] = a.y; sA[kk+2][m] = a.z; sA[kk+3][m] = a.w;
            float4 w = *(const float4*)&Wmat[(size_t)(n0+m)*K + k0 + kk];
            sW[kk][m] = w.x; sW[kk+1][m] = w.y; sW[kk+2][m] = w.z; sW[kk+3][m] = w.w;
        }
        __syncthreads();
        #pragma unroll
        for (int k = 0; k < 32; k++) {
            float4 a = *(const float4*)&sA[k][ty*4];
            float4 w = *(const float4*)&sW[k][tx*4];
            float av[4] = {a.x, a.y, a.z, a.w};
            float wv[4] = {w.x, w.y, w.z, w.w};
            #pragma unroll
            for (int i = 0; i < 4; i++)
                #pragma unroll
                for (int j = 0; j < 4; j++)
                    acc[i][j] += av[i] * wv[j];
        }
        __syncthreads();
    }
    #pragma unroll
    for (int i = 0; i < 4; i++) {
        int m = m0 + ty*4 + i;
        #pragma unroll
        for (int j = 0; j < 4; j++) {
            int n = n0 + tx*4 + j;
            Cmat[(size_t)m*N + n] = acc[i][j] + bias[n];
        }
    }
}

// ---------------- attention step (scores, softmax, ctx), 512 threads ----------
__global__ __launch_bounds__(512) void attn_kernel(int t,
        const float* __restrict__ wf, const float* __restrict__ bf_scalar,
        float* __restrict__ out_alphas) {
    int b = blockIdx.x;
    if (t >= d_declen[b]) return;
    int tid  = threadIdx.x;
    int lane = tid & 31, warp = tid >> 5;   // 16 warps

    __shared__ float4 s_da[128], s_wf[128];
    __shared__ float sc[NPIX];
    __shared__ float red_m[16], red_s[16], bc[2];

    if (tid < 128) {
        s_da[tid] = ((const float4*)d_da)[b*128 + tid];
        s_wf[tid] = ((const float4*)wf)[tid];
    }
    __syncthreads();

    const float4* ea4 = ((const float4*)d_ea) + (size_t)b*NPIX*128;
    float bfull = bf_scalar[0];
    for (int p = warp; p < NPIX; p += 16) {
        float s = 0.f;
        #pragma unroll
        for (int j = 0; j < 4; j++) {
            int k4 = lane + j*32;
            float4 e = ea4[p*128 + k4];
            float4 da = s_da[k4];
            float4 w  = s_wf[k4];
            s += fmaxf(e.x + da.x, 0.f) * w.x;
            s += fmaxf(e.y + da.y, 0.f) * w.y;
            s += fmaxf(e.z + da.z, 0.f) * w.z;
            s += fmaxf(e.w + da.w, 0.f) * w.w;
        }
        s = warp_sum(s);
        if (lane == 0) sc[p] = s + bfull;
    }
    __syncthreads();

    float v = (tid < NPIX) ? sc[tid] : -1e30f;
    float wm = warp_max(v);
    if (lane == 0) red_m[warp] = wm;
    __syncthreads();
    if (tid == 0) {
        float mm = red_m[0];
        #pragma unroll
        for (int i = 1; i < 16; i++) mm = fmaxf(mm, red_m[i]);
        bc[0] = mm;
    }
    __syncthreads();
    float gmax = bc[0];
    float e = (tid < NPIX) ? __expf(v - gmax) : 0.f;
    float ws = warp_sum(e);
    if (lane == 0) red_s[warp] = ws;
    __syncthreads();
    if (tid == 0) {
        float ss = 0.f;
        #pragma unroll
        for (int i = 0; i < 16; i++) ss += red_s[i];
        bc[1] = ss;
    }
    __syncthreads();
    float alpha = e / bc[1];
    __syncthreads();
    if (tid < NPIX) {
        sc[tid] = alpha;
        out_alphas[(size_t)b*TT*NPIX + (size_t)t*NPIX + tid] = alpha;
    }
    __syncthreads();

    // ctx[d] = gate[d] * sum_p alpha[p] * enc[b,p,d] ; one d per thread, 4-way ILP
    const float* encb = d_enc_s + (size_t)b*NPIX*512;
    float a0 = 0.f, a1 = 0.f, a2 = 0.f, a3 = 0.f;
    #pragma unroll 4
    for (int p = 0; p < 196; p += 4) {
        a0 += sc[p]   * encb[(p)  *512 + tid];
        a1 += sc[p+1] * encb[(p+1)*512 + tid];
        a2 += sc[p+2] * encb[(p+2)*512 + tid];
        a3 += sc[p+3] * encb[(p+3)*512 + tid];
    }
    d_ctx[b*512 + tid] = ((a0 + a1) + (a2 + a3)) * d_gate[b*512 + tid];
}

// ---------------- LSTM gate GEMM (split-K x4): partials ----------------------
__global__ __launch_bounds__(256) void lstm_gemm_kernel(int t,
        const float* __restrict__ emb, const float* __restrict__ Wih,
        const float* __restrict__ Whh) {
    __shared__ float sA[32][64];
    __shared__ float sW[32][64];
    __shared__ int   stok[64];
    int tid = threadIdx.x;
    if (tid < 64) stok[tid] = d_caps_s[tid*ML + t];
    __syncthreads();
    int tx = tid & 15, ty = tid >> 4;
    int n0 = blockIdx.x * 64;
    int kbase = blockIdx.y * 384;
    float acc[4][4] = {};
    for (int k0 = kbase; k0 < kbase + 384; k0 += 32) {
        #pragma unroll
        for (int u = 0; u < 2; u++) {
            int f4i = tid + u*256;
            int m  = f4i >> 3;
            int kk = (f4i & 7) << 2;
            int k  = k0 + kk;
            float4 a;
            if (k < 512)       a = *(const float4*)&emb[(size_t)stok[m]*512 + k];
            else if (k < 1024) a = *(const float4*)&d_ctx[m*512 + (k - 512)];
            else               a = *(const float4*)&d_h[m*512 + (k - 1024)];
            sA[kk][m] = a.x; sA[kk+1][m] = a.y; sA[kk+2][m] = a.z; sA[kk+3][m] = a.w;
            float4 w;
            if (k < 1024) w = *(const float4*)&Wih[(size_t)(n0+m)*1024 + k];
            else          w = *(const float4*)&Whh[(size_t)(n0+m)*512 + (k - 1024)];
            sW[kk][m] = w.x; sW[kk+1][m] = w.y; sW[kk+2][m] = w.z; sW[kk+3][m] = w.w;
        }
        __syncthreads();
        #pragma unroll
        for (int k = 0; k < 32; k++) {
            float4 a = *(const float4*)&sA[k][ty*4];
            float4 w = *(const float4*)&sW[k][tx*4];
            float av[4] = {a.x, a.y, a.z, a.w};
            float wv[4] = {w.x, w.y, w.z, w.w};
            #pragma unroll
            for (int i = 0; i < 4; i++)
                #pragma unroll
                for (int j = 0; j < 4; j++)
                    acc[i][j] += av[i] * wv[j];
        }
        __syncthreads();
    }
    float* gp = d_gates_p + (size_t)blockIdx.y * (BSZ*2048);
    #pragma unroll
    for (int i = 0; i < 4; i++) {
        int m = ty*4 + i;
        #pragma unroll
        for (int j = 0; j < 4; j++) {
            int n = n0 + tx*4 + j;
            gp[m*2048 + n] = acc[i][j];
        }
    }
}

// ---------------- LSTM pointwise (reduce split-K partials) --------------------
__global__ __launch_bounds__(256) void lstm_apply_kernel(
        const float* __restrict__ bih, const float* __restrict__ bhh) {
    int idx = blockIdx.x*256 + threadIdx.x;
    int b = idx >> 9;
    int j = idx & 511;
    float gi = 0.f, gf = 0.f, gg = 0.f, go = 0.f;
    #pragma unroll
    for (int s = 0; s < 4; s++) {
        const float* g = d_gates_p + (size_t)s*(BSZ*2048) + b*2048;
        gi += g[j];
        gf += g[512 + j];
        gg += g[1024 + j];
        go += g[1536 + j];
    }
    gi += bih[j]        + bhh[j];
    gf += bih[512 + j]  + bhh[512 + j];
    gg += bih[1024 + j] + bhh[1024 + j];
    go += bih[1536 + j] + bhh[1536 + j];
    float ig = sigmoidf_(gi);
    float fg = sigmoidf_(gf);
    float g2 = tanhf(gg);
    float og = sigmoidf_(go);
    float c  = fg * d_c[idx] + ig * g2;
    float h  = og * tanhf(c);
    d_c[idx] = c;
    d_h[idx] = h;
}

// ---------------- tail: blocks 0..15 dagate(h) ; blocks 16.. preds (tf32 mma) -
// preds tile: M=16, N=256, K tiled by 16; split-tf32 (3 mma) for fp32 accuracy.
__global__ __launch_bounds__(256) void tail_kernel(int t,
        const float* __restrict__ Wd, const float* __restrict__ bd,
        const float* __restrict__ Wg, const float* __restrict__ bg,
        const float* __restrict__ bfc, float* __restrict__ out_pred) {
    __shared__ uint32_t smem_u[2*16*20 + 2*256*20];   // 43520 B, reused by dagate
    int bx = blockIdx.x;
    int tid = threadIdx.x;

    if (bx < 16) {
        // ---- dagate: [da|gate] = h @ [Wd;Wg]^T (+bias, sigmoid on gate half) --
        float* sA = (float*)smem_u;        // [32][64] : sA[k*64+m]
        float* sW = sA + 32*64;
        int tx = tid & 15, ty = tid >> 4;
        int n0 = bx * 64;
        const float* Wmat = (n0 < 512) ? (Wd + (size_t)n0*512)
                                       : (Wg + (size_t)(n0-512)*512);
        float acc[4][4] = {};
        for (int k0 = 0; k0 < 512; k0 += 32) {
            #pragma unroll
            for (int u = 0; u < 2; u++) {
                int f4i = tid + u*256;
                int m  = f4i >> 3;
                int kk = (f4i & 7) << 2;
                float4 a = *(const float4*)&d_h[(size_t)m*512 + k0 + kk];
                sA[kk*64+m] = a.x; sA[(kk+1)*64+m] = a.y;
                sA[(kk+2)*64+m] = a.z; sA[(kk+3)*64+m] = a.w;
                float4 w = *(const float4*)&Wmat[(size_t)m*512 + k0 + kk];
                sW[kk*64+m] = w.x; sW[(kk+1)*64+m] = w.y;
                sW[(kk+2)*64+m] = w.z; sW[(kk+3)*64+m] = w.w;
            }
            __syncthreads();
            #pragma unroll
            for (int k = 0; k < 32; k++) {
                float4 a = *(const float4*)&sA[k*64 + ty*4];
                float4 w = *(const float4*)&sW[k*64 + tx*4];
                float av[4] = {a.x, a.y, a.z, a.w};
                float wv[4] = {w.x, w.y, w.z, w.w};
                #pragma unroll
                for (int i = 0; i < 4; i++)
                    #pragma unroll
                    for (int j = 0; j < 4; j++)
                        acc[i][j] += av[i] * wv[j];
            }
            __syncthreads();
        }
        #pragma unroll
        for (int i = 0; i < 4; i++) {
            int m = ty*4 + i;
            #pragma unroll
            for (int j = 0; j < 4; j++) {
                int n = n0 + tx*4 + j;
                if (n < 512) d_da[m*512 + n] = acc[i][j] + bd[n];
                else         d_gate[m*512 + (n-512)] = sigmoidf_(acc[i][j] + bg[n-512]);
            }
        }
        return;
    }

    // ---- preds: out[m, t, n] = h[m,:] @ Wfc[n,:] + bfc[n]  (split-tf32 mma) --
    int pb = bx - 16;
    int m0 = (pb & 3) * 16;
    int nact = d_nact[t];
    if (m0 >= nact) return;
    int n0 = (pb >> 2) * 256;

    uint32_t* pAh = smem_u;             // [16][20]
    uint32_t* pAl = pAh + 16*20;
    uint32_t* pWh = pAl + 16*20;        // [256][20]
    uint32_t* pWl = pWh + 256*20;

    int lane = tid & 31, w = tid >> 5;  // 8 warps, each n-width 32
    int g = lane >> 2, tig = lane & 3;
    float acc[4][4] = {};

    for (int kt = 0; kt < 32; kt++) {   // 32 k-tiles of 16
        {   // A fill: 16 rows x 16 k (256 elems, 1 per thread), split hi/lo
            int m = tid >> 4, k = tid & 15;
            float v = d_h[(m0+m)*512 + kt*16 + k];
            uint32_t hh = f2tf32(v);
            pAh[m*20 + k] = hh;
            pAl[m*20 + k] = f2tf32(v - __uint_as_float(hh));
        }
        #pragma unroll
        for (int u = 0; u < 4; u++) {   // W fill: 256 rows x 4 uint4
            int f4i = tid + u*256;
            int n  = f4i >> 2;
            int kv = f4i & 3;
            size_t gi = (size_t)(n0+n)*128 + kt*4 + kv;
            uint4 hv = d_wfh[gi];
            uint4 lv = d_wfl[gi];
            *(uint4*)&pWh[n*20 + kv*4] = hv;
            *(uint4*)&pWl[n*20 + kv*4] = lv;
        }
        __syncthreads();
        #pragma unroll
        for (int ks = 0; ks < 2; ks++) {
            int kk = ks*8;
            uint32_t ah0 = pAh[ g   *20 + kk + tig];
            uint32_t ah1 = pAh[(g+8)*20 + kk + tig];
            uint32_t ah2 = pAh[ g   *20 + kk + 4 + tig];
            uint32_t ah3 = pAh[(g+8)*20 + kk + 4 + tig];
            uint32_t al0 = pAl[ g   *20 + kk + tig];
            uint32_t al1 = pAl[(g+8)*20 + kk + tig];
            uint32_t al2 = pAl[ g   *20 + kk + 4 + tig];
            uint32_t al3 = pAl[(g+8)*20 + kk + 4 + tig];
            #pragma unroll
            for (int nf = 0; nf < 4; nf++) {
                int nrow = w*32 + nf*8 + g;
                uint32_t bh0 = pWh[nrow*20 + kk + tig];
                uint32_t bh1 = pWh[nrow*20 + kk + 4 + tig];
                uint32_t bl0 = pWl[nrow*20 + kk + tig];
                uint32_t bl1 = pWl[nrow*20 + kk + 4 + tig];
                mma_tf32(acc[nf], ah0, ah1, ah2, ah3, bh0, bh1);
                mma_tf32(acc[nf], al0, al1, al2, al3, bh0, bh1);
                mma_tf32(acc[nf], ah0, ah1, ah2, ah3, bl0, bl1);
            }
        }
        __syncthreads();
    }

    size_t tbase = (size_t)t * VV;
    #pragma unroll
    for (int nf = 0; nf < 4; nf++) {
        int n = n0 + w*32 + nf*8 + 2*tig;
        float2 bb = *(const float2*)&bfc[n];
        int m1 = m0 + g;
        if (m1 < nact) {
            float2 o; o.x = acc[nf][0] + bb.x; o.y = acc[nf][1] + bb.y;
            *(float2*)&out_pred[(size_t)m1*((size_t)TT*VV) + tbase + n] = o;
        }
        int m2 = m1 + 8;
        if (m2 < nact) {
            float2 o; o.x = acc[nf][2] + bb.x; o.y = acc[nf][3] + bb.y;
            *(float2*)&out_pred[(size_t)m2*((size_t)TT*VV) + tbase + n] = o;
        }
    }
}

// ---------------- launch ------------------------------------------------------
extern "C" void kernel_launch(void* const* d_in, const int* in_sizes, int n_in,
                              void* d_out, int out_size) {
    const float* encoder_out = (const float*)d_in[0];
    const int*   caps        = (const int*)  d_in[1];
    const int*   cap_len     = (const int*)  d_in[2];
    const float* W_enc_attn  = (const float*)d_in[3];
    const float* b_enc_attn  = (const float*)d_in[4];
    const float* W_dec_attn  = (const float*)d_in[5];
    const float* b_dec_attn  = (const float*)d_in[6];
    const float* w_full_attn = (const float*)d_in[7];
    const float* b_full_attn = (const float*)d_in[8];
    const float* emb_table   = (const float*)d_in[9];
    const float* W_ih        = (const float*)d_in[10];
    const float* W_hh        = (const float*)d_in[11];
    const float* b_ih        = (const float*)d_in[12];
    const float* b_hh        = (const float*)d_in[13];
    const float* W_init_h    = (const float*)d_in[14];
    const float* b_init_h    = (const float*)d_in[15];
    const float* W_init_c    = (const float*)d_in[16];
    const float* b_init_c    = (const float*)d_in[17];
    const float* W_f_beta    = (const float*)d_in[18];
    const float* b_f_beta    = (const float*)d_in[19];
    const float* W_fc        = (const float*)d_in[20];
    const float* b_fc        = (const float*)d_in[21];

    float* out = (float*)d_out;
    const size_t OFF_PRED   = 0;
    const size_t OFF_CAPS   = OFF_PRED + (size_t)BSZ*TT*VV;
    const size_t OFF_DECLEN = OFF_CAPS + (size_t)BSZ*ML;
    const size_t OFF_ALPHA  = OFF_DECLEN + BSZ;
    const size_t OFF_ORDER  = OFF_ALPHA + (size_t)BSZ*TT*NPIX;
    float* out_pred   = out + OFF_PRED;
    float* out_caps   = out + OFF_CAPS;
    float* out_declen = out + OFF_DECLEN;
    float* out_alphas = out + OFF_ALPHA;
    float* out_order  = out + OFF_ORDER;

    cudaMemsetAsync(d_out, 0, (size_t)out_size * sizeof(float));

    convert_wfc_kernel<<<(VV*128)/256, 256>>>((const float4*)W_fc);
    sort_kernel<<<1, 64>>>(cap_len, caps, out_caps, out_declen, out_order);
    reorder_mean_kernel<<<BSZ, 256>>>(encoder_out);

    gemm64_kernel<<<dim3(8, 196), 256>>>(0, W_enc_attn, b_enc_attn, 512, 512);
    gemm64_kernel<<<dim3(8, 1), 256>>>(1, W_init_h, b_init_h, 512, 512);
    gemm64_kernel<<<dim3(8, 1), 256>>>(2, W_init_c, b_init_c, 512, 512);
    // dagate for step 0 (tail with only dagate blocks)
    tail_kernel<<<16, 256>>>(0, W_dec_attn, b_dec_attn, W_f_beta, b_f_beta,
                             b_fc, out_pred);

    for (int t = 0; t < TT; t++) {
        attn_kernel<<<BSZ, 512>>>(t, w_full_attn, b_full_attn, out_alphas);
        lstm_gemm_kernel<<<dim3(32, 4), 256>>>(t, emb_table, W_ih, W_hh);
        lstm_apply_kernel<<<(BSZ*DD)/256, 256>>>(b_ih, b_hh);
        tail_kernel<<<16 + (VV/256)*4, 256>>>(t, W_dec_attn, b_dec_attn,
                                              W_f_beta, b_f_beta, b_fc, out_pred);
    }
}

// round 4
// speedup vs baseline: 3.1364x; 1.6795x over previous
#include <cuda_runtime.h>
#include <math.h>
#include <stdint.h>

#define BSZ 64
#define NPIX 196
#define ENCD 512
#define DD 512
#define VV 32000
#define TT 50
#define ML 51
#define NSPLIT 8

// ---------------- scratch (static device globals; no runtime alloc) ----------
__device__ float d_enc_s[BSZ*NPIX*ENCD];
__device__ float d_ea[BSZ*NPIX*ENCD];
__device__ float d_mean[BSZ*ENCD];
__device__ float d_hbuf[2][BSZ*DD];        // double-buffered h
__device__ float d_c[BSZ*DD];
__device__ float d_ctx[BSZ*ENCD];
__device__ float d_da[BSZ*DD];
__device__ float d_gate[BSZ*ENCD];
__device__ float d_gates_p[NSPLIT*BSZ*4*DD];
__device__ uint4 d_wfh[(size_t)VV*128];    // W_fc tf32 hi
__device__ uint4 d_wfl[(size_t)VV*128];    // W_fc tf32 lo
__device__ int   d_order[BSZ];
__device__ int   d_declen[BSZ];
__device__ int   d_caps_s[BSZ*ML];
__device__ int   d_nact[TT];

// ---------------- helpers ----------------------------------------------------
__device__ __forceinline__ float warp_sum(float v) {
    #pragma unroll
    for (int o = 16; o > 0; o >>= 1) v += __shfl_down_sync(0xffffffffu, v, o);
    return v;
}
__device__ __forceinline__ float warp_max(float v) {
    #pragma unroll
    for (int o = 16; o > 0; o >>= 1) v = fmaxf(v, __shfl_down_sync(0xffffffffu, v, o));
    return v;
}
__device__ __forceinline__ float sigmoidf_(float x) { return 1.0f / (1.0f + __expf(-x)); }
__device__ __forceinline__ uint32_t f2tf32(float x) {
    uint32_t r; asm("cvt.rna.tf32.f32 %0, %1;" : "=r"(r) : "f"(x)); return r;
}
__device__ __forceinline__ void mma_tf32(float c[4], uint32_t a0, uint32_t a1,
                                         uint32_t a2, uint32_t a3,
                                         uint32_t b0, uint32_t b1) {
    asm volatile(
        "mma.sync.aligned.m16n8k8.row.col.f32.tf32.tf32.f32 "
        "{%0,%1,%2,%3}, {%4,%5,%6,%7}, {%8,%9}, {%0,%1,%2,%3};\n"
        : "+f"(c[0]), "+f"(c[1]), "+f"(c[2]), "+f"(c[3])
        : "r"(a0), "r"(a1), "r"(a2), "r"(a3), "r"(b0), "r"(b1));
}

// ---------------- one-time: split W_fc into tf32 hi/lo -----------------------
__global__ __launch_bounds__(256) void convert_wfc_kernel(const float4* __restrict__ W) {
    size_t i = (size_t)blockIdx.x*256 + threadIdx.x;
    float4 v = W[i];
    uint4 h, l;
    h.x = f2tf32(v.x); l.x = f2tf32(v.x - __uint_as_float(h.x));
    h.y = f2tf32(v.y); l.y = f2tf32(v.y - __uint_as_float(h.y));
    h.z = f2tf32(v.z); l.z = f2tf32(v.z - __uint_as_float(h.z));
    h.w = f2tf32(v.w); l.w = f2tf32(v.w - __uint_as_float(h.w));
    d_wfh[i] = h; d_wfl[i] = l;
}

// ---------------- sort (stable, descending cap_len) ---------------------------
__global__ void sort_kernel(const int* __restrict__ cap_len,
                            const int* __restrict__ caps,
                            float* __restrict__ out_caps,
                            float* __restrict__ out_declen,
                            float* __restrict__ out_order) {
    int i = threadIdx.x;
    int cl = cap_len[i];
    int r = 0;
    for (int j = 0; j < BSZ; j++) {
        int cj = cap_len[j];
        if (cj > cl || (cj == cl && j < i)) r++;
    }
    d_order[r]  = i;
    d_declen[r] = cl - 1;
    __syncthreads();
    out_order[i]  = (float)d_order[i];
    out_declen[i] = (float)d_declen[i];
    int src = d_order[i];
    for (int tt = 0; tt < ML; tt++) {
        int tok = caps[src*ML + tt];
        d_caps_s[i*ML + tt] = tok;
        out_caps[i*ML + tt] = (float)tok;
    }
    if (i < TT) {
        int cnt = 0;
        for (int j = 0; j < BSZ; j++) if (d_declen[j] > i) cnt++;
        d_nact[i] = cnt;
    }
}

// ---------------- reorder encoder + per-batch pixel mean ----------------------
__global__ __launch_bounds__(256) void reorder_mean_kernel(const float* __restrict__ enc) {
    int b = blockIdx.x;
    int tid = threadIdx.x;
    int src = d_order[b];
    const float* Ein = enc + (size_t)src*NPIX*ENCD;
    float* Eo = d_enc_s + (size_t)b*NPIX*ENCD;
    float s0 = 0.f, s1 = 0.f;
    for (int p = 0; p < NPIX; p++) {
        float v0 = Ein[p*ENCD + tid];
        float v1 = Ein[p*ENCD + tid + 256];
        Eo[p*ENCD + tid]       = v0;
        Eo[p*ENCD + tid + 256] = v1;
        s0 += v0; s1 += v1;
    }
    d_mean[b*ENCD + tid]       = s0 * (1.0f/NPIX);
    d_mean[b*ENCD + tid + 256] = s1 * (1.0f/NPIX);
}

// ---------------- generic 64x64 tiled GEMM: C = A @ W^T + bias ---------------
// sel: 0 -> ea ; 1 -> h0 (hbuf[0]) ; 2 -> c0
__global__ __launch_bounds__(256) void gemm64_kernel(int sel,
        const float* __restrict__ Wmat, const float* __restrict__ bias,
        int K, int N) {
    const float* Amat = (sel == 0) ? d_enc_s : d_mean;
    float*       Cmat = (sel == 0) ? d_ea : ((sel == 1) ? d_hbuf[0] : d_c);
    __shared__ float sA[32][64];
    __shared__ float sW[32][64];
    int tid = threadIdx.x;
    int tx = tid & 15, ty = tid >> 4;
    int m0 = blockIdx.y * 64;
    int n0 = blockIdx.x * 64;
    float acc[4][4] = {};
    for (int k0 = 0; k0 < K; k0 += 32) {
        #pragma unroll
        for (int u = 0; u < 2; u++) {
            int f4i = tid + u*256;
            int m  = f4i >> 3;
            int kk = (f4i & 7) << 2;
            float4 a = *(const float4*)&Amat[(size_t)(m0+m)*K + k0 + kk];
            sA[kk][m] = a.x; sA[kk+1][m] = a.y; sA[kk+2][m] = a.z; sA[kk+3][m] = a.w;
            float4 w = *(const float4*)&Wmat[(size_t)(n0+m)*K + k0 + kk];
            sW[kk][m] = w.x; sW[kk+1][m] = w.y; sW[kk+2][m] = w.z; sW[kk+3][m] = w.w;
        }
        __syncthreads();
        #pragma unroll
        for (int k = 0; k < 32; k++) {
            float4 a = *(const float4*)&sA[k][ty*4];
            float4 w = *(const float4*)&sW[k][tx*4];
            float av[4] = {a.x, a.y, a.z, a.w};
            float wv[4] = {w.x, w.y, w.z, w.w};
            #pragma unroll
            for (int i = 0; i < 4; i++)
                #pragma unroll
                for (int j = 0; j < 4; j++)
                    acc[i][j] += av[i] * wv[j];
        }
        __syncthreads();
    }
    #pragma unroll
    for (int i = 0; i < 4; i++) {
        int m = m0 + ty*4 + i;
        #pragma unroll
        for (int j = 0; j < 4; j++) {
            int n = n0 + tx*4 + j;
            Cmat[(size_t)m*N + n] = acc[i][j] + bias[n];
        }
    }
}

// ---------------- dagate: [da|gate] = h @ [Wd;Wg]^T (reads hbuf[hb]) ----------
__global__ __launch_bounds__(256) void dagate_kernel(int hb,
        const float* __restrict__ Wd, const float* __restrict__ bd,
        const float* __restrict__ Wg, const float* __restrict__ bg) {
    __shared__ float sA[32][64];
    __shared__ float sW[32][64];
    const float* hsrc = d_hbuf[hb];
    int tid = threadIdx.x;
    int tx = tid & 15, ty = tid >> 4;
    int n0 = blockIdx.x * 64;
    const float* Wmat = (n0 < 512) ? (Wd + (size_t)n0*512) : (Wg + (size_t)(n0-512)*512);
    float acc[4][4] = {};
    for (int k0 = 0; k0 < 512; k0 += 32) {
        #pragma unroll
        for (int u = 0; u < 2; u++) {
            int f4i = tid + u*256;
            int m  = f4i >> 3;
            int kk = (f4i & 7) << 2;
            float4 a = *(const float4*)&hsrc[(size_t)m*512 + k0 + kk];
            sA[kk][m] = a.x; sA[kk+1][m] = a.y; sA[kk+2][m] = a.z; sA[kk+3][m] = a.w;
            float4 w = *(const float4*)&Wmat[(size_t)m*512 + k0 + kk];
            sW[kk][m] = w.x; sW[kk+1][m] = w.y; sW[kk+2][m] = w.z; sW[kk+3][m] = w.w;
        }
        __syncthreads();
        #pragma unroll
        for (int k = 0; k < 32; k++) {
            float4 a = *(const float4*)&sA[k][ty*4];
            float4 w = *(const float4*)&sW[k][tx*4];
            float av[4] = {a.x, a.y, a.z, a.w};
            float wv[4] = {w.x, w.y, w.z, w.w};
            #pragma unroll
            for (int i = 0; i < 4; i++)
                #pragma unroll
                for (int j = 0; j < 4; j++)
                    acc[i][j] += av[i] * wv[j];
        }
        __syncthreads();
    }
    #pragma unroll
    for (int i = 0; i < 4; i++) {
        int m = ty*4 + i;
        #pragma unroll
        for (int j = 0; j < 4; j++) {
            int n = n0 + tx*4 + j;
            if (n < 512) d_da[m*512 + n] = acc[i][j] + bd[n];
            else         d_gate[m*512 + (n-512)] = sigmoidf_(acc[i][j] + bg[n-512]);
        }
    }
}

// ---------------- attention step (scores, softmax, ctx), 512 threads ----------
__global__ __launch_bounds__(512) void attn_kernel(int t,
        const float* __restrict__ wf, const float* __restrict__ bf_scalar,
        float* __restrict__ out_alphas) {
    int b = blockIdx.x;
    if (t >= d_declen[b]) return;
    int tid  = threadIdx.x;
    int lane = tid & 31, warp = tid >> 5;

    __shared__ float4 s_da[128], s_wf[128];
    __shared__ float sc[NPIX];
    __shared__ float red_m[16], red_s[16], bc[2];

    if (tid < 128) {
        s_da[tid] = ((const float4*)d_da)[b*128 + tid];
        s_wf[tid] = ((const float4*)wf)[tid];
    }
    __syncthreads();

    const float4* ea4 = ((const float4*)d_ea) + (size_t)b*NPIX*128;
    float bfull = bf_scalar[0];
    for (int p = warp; p < NPIX; p += 16) {
        float s = 0.f;
        #pragma unroll
        for (int j = 0; j < 4; j++) {
            int k4 = lane + j*32;
            float4 e = ea4[p*128 + k4];
            float4 da = s_da[k4];
            float4 w  = s_wf[k4];
            s += fmaxf(e.x + da.x, 0.f) * w.x;
            s += fmaxf(e.y + da.y, 0.f) * w.y;
            s += fmaxf(e.z + da.z, 0.f) * w.z;
            s += fmaxf(e.w + da.w, 0.f) * w.w;
        }
        s = warp_sum(s);
        if (lane == 0) sc[p] = s + bfull;
    }
    __syncthreads();

    float v = (tid < NPIX) ? sc[tid] : -1e30f;
    float wm = warp_max(v);
    if (lane == 0) red_m[warp] = wm;
    __syncthreads();
    if (tid == 0) {
        float mm = red_m[0];
        #pragma unroll
        for (int i = 1; i < 16; i++) mm = fmaxf(mm, red_m[i]);
        bc[0] = mm;
    }
    __syncthreads();
    float gmax = bc[0];
    float e = (tid < NPIX) ? __expf(v - gmax) : 0.f;
    float ws = warp_sum(e);
    if (lane == 0) red_s[warp] = ws;
    __syncthreads();
    if (tid == 0) {
        float ss = 0.f;
        #pragma unroll
        for (int i = 0; i < 16; i++) ss += red_s[i];
        bc[1] = ss;
    }
    __syncthreads();
    float alpha = e / bc[1];
    __syncthreads();
    if (tid < NPIX) {
        sc[tid] = alpha;
        out_alphas[(size_t)b*TT*NPIX + (size_t)t*NPIX + tid] = alpha;
    }
    __syncthreads();

    const float* encb = d_enc_s + (size_t)b*NPIX*512;
    float a0 = 0.f, a1 = 0.f, a2 = 0.f, a3 = 0.f;
    #pragma unroll 4
    for (int p = 0; p < 196; p += 4) {
        a0 += sc[p]   * encb[(p)  *512 + tid];
        a1 += sc[p+1] * encb[(p+1)*512 + tid];
        a2 += sc[p+2] * encb[(p+2)*512 + tid];
        a3 += sc[p+3] * encb[(p+3)*512 + tid];
    }
    d_ctx[b*512 + tid] = ((a0 + a1) + (a2 + a3)) * d_gate[b*512 + tid];
}

// ---------------- LSTM gate GEMM (split-K x8): partials -----------------------
__global__ __launch_bounds__(256) void lstm_gemm_kernel(int t, int hb,
        const float* __restrict__ emb, const float* __restrict__ Wih,
        const float* __restrict__ Whh) {
    __shared__ float sA[32][64];
    __shared__ float sW[32][64];
    __shared__ int   stok[64];
    const float* hsrc = d_hbuf[hb];
    int tid = threadIdx.x;
    if (tid < 64) stok[tid] = d_caps_s[tid*ML + t];
    __syncthreads();
    int tx = tid & 15, ty = tid >> 4;
    int n0 = blockIdx.x * 64;
    int kbase = blockIdx.y * 192;
    float acc[4][4] = {};
    for (int k0 = kbase; k0 < kbase + 192; k0 += 32) {
        #pragma unroll
        for (int u = 0; u < 2; u++) {
            int f4i = tid + u*256;
            int m  = f4i >> 3;
            int kk = (f4i & 7) << 2;
            int k  = k0 + kk;
            float4 a;
            if (k < 512)       a = *(const float4*)&emb[(size_t)stok[m]*512 + k];
            else if (k < 1024) a = *(const float4*)&d_ctx[m*512 + (k - 512)];
            else               a = *(const float4*)&hsrc[m*512 + (k - 1024)];
            sA[kk][m] = a.x; sA[kk+1][m] = a.y; sA[kk+2][m] = a.z; sA[kk+3][m] = a.w;
            float4 w;
            if (k < 1024) w = *(const float4*)&Wih[(size_t)(n0+m)*1024 + k];
            else          w = *(const float4*)&Whh[(size_t)(n0+m)*512 + (k - 1024)];
            sW[kk][m] = w.x; sW[kk+1][m] = w.y; sW[kk+2][m] = w.z; sW[kk+3][m] = w.w;
        }
        __syncthreads();
        #pragma unroll
        for (int k = 0; k < 32; k++) {
            float4 a = *(const float4*)&sA[k][ty*4];
            float4 w = *(const float4*)&sW[k][tx*4];
            float av[4] = {a.x, a.y, a.z, a.w};
            float wv[4] = {w.x, w.y, w.z, w.w};
            #pragma unroll
            for (int i = 0; i < 4; i++)
                #pragma unroll
                for (int j = 0; j < 4; j++)
                    acc[i][j] += av[i] * wv[j];
        }
        __syncthreads();
    }
    float* gp = d_gates_p + (size_t)blockIdx.y * (BSZ*2048);
    #pragma unroll
    for (int i = 0; i < 4; i++) {
        int m = ty*4 + i;
        #pragma unroll
        for (int j = 0; j < 4; j++) {
            int n = n0 + tx*4 + j;
            gp[m*2048 + n] = acc[i][j];
        }
    }
}

// ---------------- LSTM pointwise (reduce split-K partials) --------------------
__global__ __launch_bounds__(256) void lstm_apply_kernel(int hbw,
        const float* __restrict__ bih, const float* __restrict__ bhh) {
    int idx = blockIdx.x*256 + threadIdx.x;
    int b = idx >> 9;
    int j = idx & 511;
    float gi = 0.f, gf = 0.f, gg = 0.f, go = 0.f;
    #pragma unroll
    for (int s = 0; s < NSPLIT; s++) {
        const float* g = d_gates_p + (size_t)s*(BSZ*2048) + b*2048;
        gi += g[j];
        gf += g[512 + j];
        gg += g[1024 + j];
        go += g[1536 + j];
    }
    gi += bih[j]        + bhh[j];
    gf += bih[512 + j]  + bhh[512 + j];
    gg += bih[1024 + j] + bhh[1024 + j];
    go += bih[1536 + j] + bhh[1536 + j];
    float ig = sigmoidf_(gi);
    float fg = sigmoidf_(gf);
    float g2 = tanhf(gg);
    float og = sigmoidf_(go);
    float c  = fg * d_c[idx] + ig * g2;
    float h  = og * tanhf(c);
    d_c[idx] = c;
    d_hbuf[hbw][idx] = h;
}

// ---------------- preds: 64 x 32000 x 512, split-tf32 mma, M=64/N=256 tiles ---
__global__ __launch_bounds__(256) void preds_kernel(int t, int hb,
        const float* __restrict__ bfc, float* __restrict__ out_pred) {
    extern __shared__ uint32_t sm[];
    uint32_t* Ah = sm;                  // [64][36]
    uint32_t* Al = Ah + 64*36;
    uint32_t* Wh = Al + 64*36;          // [256][36]
    uint32_t* Wl = Wh + 256*36;

    int nact = d_nact[t];
    int n0 = blockIdx.x * 256;
    int tid = threadIdx.x;
    int lane = tid & 31, w = tid >> 5;
    int g = lane >> 2, tig = lane & 3;
    const float* hsrc = d_hbuf[hb];

    float acc[4][4][4];
    #pragma unroll
    for (int a = 0; a < 4; a++)
        #pragma unroll
        for (int b2 = 0; b2 < 4; b2++)
            #pragma unroll
            for (int c2 = 0; c2 < 4; c2++) acc[a][b2][c2] = 0.f;

    for (int kt = 0; kt < 16; kt++) {   // K=512 in tiles of 32
        // A fill: 64 rows x 32 k -> split hi/lo. 2048 floats; 8 per thread.
        #pragma unroll
        for (int u = 0; u < 2; u++) {
            int f = tid*8 + u*4;        // why *8: thread covers 8 floats; here 2x float4
            int row = f >> 5;
            int col = f & 31;
            float4 v = *(const float4*)&hsrc[row*512 + kt*32 + col];
            uint4 hh, ll;
            hh.x = f2tf32(v.x); ll.x = f2tf32(v.x - __uint_as_float(hh.x));
            hh.y = f2tf32(v.y); ll.y = f2tf32(v.y - __uint_as_float(hh.y));
            hh.z = f2tf32(v.z); ll.z = f2tf32(v.z - __uint_as_float(hh.z));
            hh.w = f2tf32(v.w); ll.w = f2tf32(v.w - __uint_as_float(hh.w));
            *(uint4*)&Ah[row*36 + col] = hh;
            *(uint4*)&Al[row*36 + col] = ll;
        }
        // W fill: 256 rows x 32 k hi+lo = 2048 uint4 each; 8 uint4/thread each.
        #pragma unroll
        for (int u = 0; u < 8; u++) {
            int f4 = tid + u*256;
            int n  = f4 >> 3;
            int kv = f4 & 7;
            size_t gi = (size_t)(n0+n)*128 + kt*8 + kv;
            *(uint4*)&Wh[n*36 + kv*4] = d_wfh[gi];
            *(uint4*)&Wl[n*36 + kv*4] = d_wfl[gi];
        }
        __syncthreads();
        #pragma unroll
        for (int ks = 0; ks < 4; ks++) {
            int kk = ks*8;
            uint32_t ah[4][4], al[4][4];
            #pragma unroll
            for (int mf = 0; mf < 4; mf++) {
                int r0 = (mf*16 + g)*36 + kk + tig;
                int r1 = (mf*16 + g + 8)*36 + kk + tig;
                ah[mf][0] = Ah[r0];   ah[mf][1] = Ah[r1];
                ah[mf][2] = Ah[r0+4]; ah[mf][3] = Ah[r1+4];
                al[mf][0] = Al[r0];   al[mf][1] = Al[r1];
                al[mf][2] = Al[r0+4]; al[mf][3] = Al[r1+4];
            }
            #pragma unroll
            for (int nf = 0; nf < 4; nf++) {
                int rw = (w*32 + nf*8 + g)*36 + kk + tig;
                uint32_t bh0 = Wh[rw], bh1 = Wh[rw+4];
                uint32_t bl0 = Wl[rw], bl1 = Wl[rw+4];
                #pragma unroll
                for (int mf = 0; mf < 4; mf++) {
                    mma_tf32(acc[mf][nf], ah[mf][0], ah[mf][1], ah[mf][2], ah[mf][3], bh0, bh1);
                    mma_tf32(acc[mf][nf], al[mf][0], al[mf][1], al[mf][2], al[mf][3], bh0, bh1);
                    mma_tf32(acc[mf][nf], ah[mf][0], ah[mf][1], ah[mf][2], ah[mf][3], bl0, bl1);
                }
            }
        }
        __syncthreads();
    }

    size_t tbase = (size_t)t * VV;
    #pragma unroll
    for (int nf = 0; nf < 4; nf++) {
        int n = n0 + w*32 + nf*8 + 2*tig;
        float2 bb = *(const float2*)&bfc[n];
        #pragma unroll
        for (int mf = 0; mf < 4; mf++) {
            int m1 = mf*16 + g;
            if (m1 < nact) {
                float2 o; o.x = acc[mf][nf][0] + bb.x; o.y = acc[mf][nf][1] + bb.y;
                *(float2*)&out_pred[(size_t)m1*((size_t)TT*VV) + tbase + n] = o;
            }
            int m2 = m1 + 8;
            if (m2 < nact) {
                float2 o; o.x = acc[mf][nf][2] + bb.x; o.y = acc[mf][nf][3] + bb.y;
                *(float2*)&out_pred[(size_t)m2*((size_t)TT*VV) + tbase + n] = o;
            }
        }
    }
}

// ---------------- launch ------------------------------------------------------
extern "C" void kernel_launch(void* const* d_in, const int* in_sizes, int n_in,
                              void* d_out, int out_size) {
    const float* encoder_out = (const float*)d_in[0];
    const int*   caps        = (const int*)  d_in[1];
    const int*   cap_len     = (const int*)  d_in[2];
    const float* W_enc_attn  = (const float*)d_in[3];
    const float* b_enc_attn  = (const float*)d_in[4];
    const float* W_dec_attn  = (const float*)d_in[5];
    const float* b_dec_attn  = (const float*)d_in[6];
    const float* w_full_attn = (const float*)d_in[7];
    const float* b_full_attn = (const float*)d_in[8];
    const float* emb_table   = (const float*)d_in[9];
    const float* W_ih        = (const float*)d_in[10];
    const float* W_hh        = (const float*)d_in[11];
    const float* b_ih        = (const float*)d_in[12];
    const float* b_hh        = (const float*)d_in[13];
    const float* W_init_h    = (const float*)d_in[14];
    const float* b_init_h    = (const float*)d_in[15];
    const float* W_init_c    = (const float*)d_in[16];
    const float* b_init_c    = (const float*)d_in[17];
    const float* W_f_beta    = (const float*)d_in[18];
    const float* b_f_beta    = (const float*)d_in[19];
    const float* W_fc        = (const float*)d_in[20];
    const float* b_fc        = (const float*)d_in[21];

    float* out = (float*)d_out;
    const size_t OFF_PRED   = 0;
    const size_t OFF_CAPS   = OFF_PRED + (size_t)BSZ*TT*VV;
    const size_t OFF_DECLEN = OFF_CAPS + (size_t)BSZ*ML;
    const size_t OFF_ALPHA  = OFF_DECLEN + BSZ;
    const size_t OFF_ORDER  = OFF_ALPHA + (size_t)BSZ*TT*NPIX;
    float* out_pred   = out + OFF_PRED;
    float* out_caps   = out + OFF_CAPS;
    float* out_declen = out + OFF_DECLEN;
    float* out_alphas = out + OFF_ALPHA;
    float* out_order  = out + OFF_ORDER;

    // one-time host-side setup (streams/events/attrs); no device allocation
    static cudaStream_t s1 = nullptr, s2 = nullptr;
    static cudaEvent_t evFork, evEnd1, evEnd2;
    static cudaEvent_t evH[TT], evP[TT];
    static bool inited = false;
    if (!inited) {
        cudaStreamCreateWithFlags(&s1, cudaStreamNonBlocking);
        cudaStreamCreateWithFlags(&s2, cudaStreamNonBlocking);
        cudaEventCreateWithFlags(&evFork, cudaEventDisableTiming);
        cudaEventCreateWithFlags(&evEnd1, cudaEventDisableTiming);
        cudaEventCreateWithFlags(&evEnd2, cudaEventDisableTiming);
        for (int i = 0; i < TT; i++) {
            cudaEventCreateWithFlags(&evH[i], cudaEventDisableTiming);
            cudaEventCreateWithFlags(&evP[i], cudaEventDisableTiming);
        }
        cudaFuncSetAttribute(preds_kernel, cudaFuncAttributeMaxDynamicSharedMemorySize,
                             (64*36*2 + 256*36*2) * 4);
        inited = true;
    }
    const int PREDS_SMEM = (64*36*2 + 256*36*2) * 4;   // 92160 B

    cudaMemsetAsync(d_out, 0, (size_t)out_size * sizeof(float));

    convert_wfc_kernel<<<(VV*128)/256, 256>>>((const float4*)W_fc);
    sort_kernel<<<1, 64>>>(cap_len, caps, out_caps, out_declen, out_order);
    reorder_mean_kernel<<<BSZ, 256>>>(encoder_out);
    gemm64_kernel<<<dim3(8, 196), 256>>>(0, W_enc_attn, b_enc_attn, 512, 512);
    gemm64_kernel<<<dim3(8, 1), 256>>>(1, W_init_h, b_init_h, 512, 512);
    gemm64_kernel<<<dim3(8, 1), 256>>>(2, W_init_c, b_init_c, 512, 512);
    dagate_kernel<<<16, 256>>>(0, W_dec_attn, b_dec_attn, W_f_beta, b_f_beta);

    // fork into two streams
    cudaEventRecord(evFork, 0);
    cudaStreamWaitEvent(s1, evFork, 0);
    cudaStreamWaitEvent(s2, evFork, 0);

    for (int t = 0; t < TT; t++) {
        int hb  = t & 1;          // h_t
        int hbw = (t + 1) & 1;    // h_{t+1}
        attn_kernel<<<BSZ, 512, 0, s1>>>(t, w_full_attn, b_full_attn, out_alphas);
        lstm_gemm_kernel<<<dim3(32, NSPLIT), 256, 0, s1>>>(t, hb, emb_table, W_ih, W_hh);
        if (t >= 2) cudaStreamWaitEvent(s1, evP[t-2], 0);   // WAR: preds(t-2) reads hbuf[hbw]
        lstm_apply_kernel<<<(BSZ*DD)/256, 256, 0, s1>>>(hbw, b_ih, b_hh);
        cudaEventRecord(evH[t], s1);
        dagate_kernel<<<16, 256, 0, s1>>>(hbw, W_dec_attn, b_dec_attn, W_f_beta, b_f_beta);

        cudaStreamWaitEvent(s2, evH[t], 0);
        preds_kernel<<<VV/256, 256, PREDS_SMEM, s2>>>(t, hbw, b_fc, out_pred);
        cudaEventRecord(evP[t], s2);
    }

    // join back to the origin (capture) stream
    cudaEventRecord(evEnd1, s1);
    cudaEventRecord(evEnd2, s2);
    cudaStreamWaitEvent((cudaStream_t)0, evEnd1, 0);
    cudaStreamWaitEvent((cudaStream_t)0, evEnd2, 0);
}

// round 5
// speedup vs baseline: 3.1718x; 1.0113x over previous
#include <cuda_runtime.h>
#include <cuda_bf16.h>
#include <cuda_pipeline.h>
#include <math.h>
#include <stdint.h>

#define BSZ 64
#define NPIX 196
#define ENCD 512
#define DD 512
#define VV 32000
#define TT 50
#define ML 51
#define NSPLIT 8

// ---------------- scratch (static device globals; no runtime alloc) ----------
__device__ float d_enc_s[BSZ*NPIX*ENCD];
__device__ float d_ea[BSZ*NPIX*ENCD];
__device__ float d_mean[BSZ*ENCD];
__device__ float d_hbuf[2][BSZ*DD];          // double-buffered h (f32)
__device__ uint32_t d_hph[2][BSZ*DD/2];      // h packed bf16-hi pairs
__device__ uint32_t d_hpl[2][BSZ*DD/2];      // h packed bf16-lo pairs
__device__ float d_c[BSZ*DD];
__device__ float d_ctx[BSZ*ENCD];
__device__ float d_da[BSZ*DD];
__device__ float d_gate[BSZ*ENCD];
__device__ float d_gates_p[NSPLIT*BSZ*4*DD];
__device__ uint32_t d_wfh16[(size_t)VV*256];  // W_fc bf16 hi, k-pairs packed (32.8MB)
__device__ uint32_t d_wfl16[(size_t)VV*256];  // W_fc bf16 lo (32.8MB)
__device__ unsigned int d_bar;                // monotonic ticket barrier
__device__ int   d_order[BSZ];
__device__ int   d_declen[BSZ];
__device__ int   d_caps_s[BSZ*ML];
__device__ int   d_nact[TT];

// ---------------- helpers ----------------------------------------------------
__device__ __forceinline__ float warp_sum(float v) {
    #pragma unroll
    for (int o = 16; o > 0; o >>= 1) v += __shfl_down_sync(0xffffffffu, v, o);
    return v;
}
__device__ __forceinline__ float warp_max(float v) {
    #pragma unroll
    for (int o = 16; o > 0; o >>= 1) v = fmaxf(v, __shfl_down_sync(0xffffffffu, v, o));
    return v;
}
__device__ __forceinline__ float sigmoidf_(float x) { return 1.0f / (1.0f + __expf(-x)); }

// split (a,b) into packed bf16 hi and bf16 lo pair-words (low 16 bits = a)
__device__ __forceinline__ void bfsplit2(float a, float b, uint32_t& hi, uint32_t& lo) {
    __nv_bfloat162 h2 = __floats2bfloat162_rn(a, b);
    float ra = a - __bfloat162float(h2.x);
    float rb = b - __bfloat162float(h2.y);
    __nv_bfloat162 l2 = __floats2bfloat162_rn(ra, rb);
    hi = *(uint32_t*)&h2;
    lo = *(uint32_t*)&l2;
}

__device__ __forceinline__ void mma_bf16(float c[4], uint32_t a0, uint32_t a1,
                                         uint32_t a2, uint32_t a3,
                                         uint32_t b0, uint32_t b1) {
    asm volatile(
        "mma.sync.aligned.m16n8k16.row.col.f32.bf16.bf16.f32 "
        "{%0,%1,%2,%3}, {%4,%5,%6,%7}, {%8,%9}, {%0,%1,%2,%3};\n"
        : "+f"(c[0]), "+f"(c[1]), "+f"(c[2]), "+f"(c[3])
        : "r"(a0), "r"(a1), "r"(a2), "r"(a3), "r"(b0), "r"(b1));
}

// ---------------- one-time: split W_fc into packed bf16 hi/lo -----------------
__global__ __launch_bounds__(256) void convert_wfc_kernel(const float4* __restrict__ W) {
    size_t gi = (size_t)blockIdx.x*256 + threadIdx.x;   // uint4 index over VV*64
    float4 v0 = W[gi*2];
    float4 v1 = W[gi*2+1];
    uint4 h, l;
    bfsplit2(v0.x, v0.y, h.x, l.x);
    bfsplit2(v0.z, v0.w, h.y, l.y);
    bfsplit2(v1.x, v1.y, h.z, l.z);
    bfsplit2(v1.z, v1.w, h.w, l.w);
    ((uint4*)d_wfh16)[gi] = h;
    ((uint4*)d_wfl16)[gi] = l;
}

// ---------------- pack h0 into bf16 hi/lo -------------------------------------
__global__ __launch_bounds__(256) void convert_h0_kernel() {
    int pid = blockIdx.x*256 + threadIdx.x;   // 16384 pairs
    float a = d_hbuf[0][pid*2];
    float b = d_hbuf[0][pid*2+1];
    uint32_t hi, lo;
    bfsplit2(a, b, hi, lo);
    d_hph[0][pid] = hi;
    d_hpl[0][pid] = lo;
}

// ---------------- sort (stable, descending cap_len) ---------------------------
__global__ void sort_kernel(const int* __restrict__ cap_len,
                            const int* __restrict__ caps,
                            float* __restrict__ out_caps,
                            float* __restrict__ out_declen,
                            float* __restrict__ out_order) {
    int i = threadIdx.x;
    int cl = cap_len[i];
    int r = 0;
    for (int j = 0; j < BSZ; j++) {
        int cj = cap_len[j];
        if (cj > cl || (cj == cl && j < i)) r++;
    }
    d_order[r]  = i;
    d_declen[r] = cl - 1;
    __syncthreads();
    out_order[i]  = (float)d_order[i];
    out_declen[i] = (float)d_declen[i];
    int src = d_order[i];
    for (int tt = 0; tt < ML; tt++) {
        int tok = caps[src*ML + tt];
        d_caps_s[i*ML + tt] = tok;
        out_caps[i*ML + tt] = (float)tok;
    }
    if (i < TT) {
        int cnt = 0;
        for (int j = 0; j < BSZ; j++) if (d_declen[j] > i) cnt++;
        d_nact[i] = cnt;
    }
}

// ---------------- reorder encoder + per-batch pixel mean ----------------------
__global__ __launch_bounds__(256) void reorder_mean_kernel(const float* __restrict__ enc) {
    int b = blockIdx.x;
    int tid = threadIdx.x;
    int src = d_order[b];
    const float* Ein = enc + (size_t)src*NPIX*ENCD;
    float* Eo = d_enc_s + (size_t)b*NPIX*ENCD;
    float s0 = 0.f, s1 = 0.f;
    for (int p = 0; p < NPIX; p++) {
        float v0 = Ein[p*ENCD + tid];
        float v1 = Ein[p*ENCD + tid + 256];
        Eo[p*ENCD + tid]       = v0;
        Eo[p*ENCD + tid + 256] = v1;
        s0 += v0; s1 += v1;
    }
    d_mean[b*ENCD + tid]       = s0 * (1.0f/NPIX);
    d_mean[b*ENCD + tid + 256] = s1 * (1.0f/NPIX);
}

// ---------------- generic 64x64 tiled GEMM: C = A @ W^T + bias ---------------
// sel: 0 -> ea ; 1 -> h0 (hbuf[0]) ; 2 -> c0
__global__ __launch_bounds__(256) void gemm64_kernel(int sel,
        const float* __restrict__ Wmat, const float* __restrict__ bias,
        int K, int N) {
    const float* Amat = (sel == 0) ? d_enc_s : d_mean;
    float*       Cmat = (sel == 0) ? d_ea : ((sel == 1) ? d_hbuf[0] : d_c);
    __shared__ float sA[32][64];
    __shared__ float sW[32][64];
    int tid = threadIdx.x;
    int tx = tid & 15, ty = tid >> 4;
    int m0 = blockIdx.y * 64;
    int n0 = blockIdx.x * 64;
    float acc[4][4] = {};
    for (int k0 = 0; k0 < K; k0 += 32) {
        #pragma unroll
        for (int u = 0; u < 2; u++) {
            int f4i = tid + u*256;
            int m  = f4i >> 3;
            int kk = (f4i & 7) << 2;
            float4 a = *(const float4*)&Amat[(size_t)(m0+m)*K + k0 + kk];
            sA[kk][m] = a.x; sA[kk+1][m] = a.y; sA[kk+2][m] = a.z; sA[kk+3][m] = a.w;
            float4 w = *(const float4*)&Wmat[(size_t)(n0+m)*K + k0 + kk];
            sW[kk][m] = w.x; sW[kk+1][m] = w.y; sW[kk+2][m] = w.z; sW[kk+3][m] = w.w;
        }
        __syncthreads();
        #pragma unroll
        for (int k = 0; k < 32; k++) {
            float4 a = *(const float4*)&sA[k][ty*4];
            float4 w = *(const float4*)&sW[k][tx*4];
            float av[4] = {a.x, a.y, a.z, a.w};
            float wv[4] = {w.x, w.y, w.z, w.w};
            #pragma unroll
            for (int i = 0; i < 4; i++)
                #pragma unroll
                for (int j = 0; j < 4; j++)
                    acc[i][j] += av[i] * wv[j];
        }
        __syncthreads();
    }
    #pragma unroll
    for (int i = 0; i < 4; i++) {
        int m = m0 + ty*4 + i;
        #pragma unroll
        for (int j = 0; j < 4; j++) {
            int n = n0 + tx*4 + j;
            Cmat[(size_t)m*N + n] = acc[i][j] + bias[n];
        }
    }
}

// ---------------- standalone dagate (step-0 prologue) -------------------------
__global__ __launch_bounds__(256) void dagate_kernel(int hb,
        const float* __restrict__ Wd, const float* __restrict__ bd,
        const float* __restrict__ Wg, const float* __restrict__ bg) {
    __shared__ float sA[32][64];
    __shared__ float sW[32][64];
    const float* hsrc = d_hbuf[hb];
    int tid = threadIdx.x;
    int tx = tid & 15, ty = tid >> 4;
    int n0 = blockIdx.x * 64;
    const float* Wmat = (n0 < 512) ? (Wd + (size_t)n0*512) : (Wg + (size_t)(n0-512)*512);
    float acc[4][4] = {};
    for (int k0 = 0; k0 < 512; k0 += 32) {
        #pragma unroll
        for (int u = 0; u < 2; u++) {
            int f4i = tid + u*256;
            int m  = f4i >> 3;
            int kk = (f4i & 7) << 2;
            float4 a = *(const float4*)&hsrc[(size_t)m*512 + k0 + kk];
            sA[kk][m] = a.x; sA[kk+1][m] = a.y; sA[kk+2][m] = a.z; sA[kk+3][m] = a.w;
            float4 w = *(const float4*)&Wmat[(size_t)m*512 + k0 + kk];
            sW[kk][m] = w.x; sW[kk+1][m] = w.y; sW[kk+2][m] = w.z; sW[kk+3][m] = w.w;
        }
        __syncthreads();
        #pragma unroll
        for (int k = 0; k < 32; k++) {
            float4 a = *(const float4*)&sA[k][ty*4];
            float4 w = *(const float4*)&sW[k][tx*4];
            float av[4] = {a.x, a.y, a.z, a.w};
            float wv[4] = {w.x, w.y, w.z, w.w};
            #pragma unroll
            for (int i = 0; i < 4; i++)
                #pragma unroll
                for (int j = 0; j < 4; j++)
                    acc[i][j] += av[i] * wv[j];
        }
        __syncthreads();
    }
    #pragma unroll
    for (int i = 0; i < 4; i++) {
        int m = ty*4 + i;
        #pragma unroll
        for (int j = 0; j < 4; j++) {
            int n = n0 + tx*4 + j;
            if (n < 512) d_da[m*512 + n] = acc[i][j] + bd[n];
            else         d_gate[m*512 + (n-512)] = sigmoidf_(acc[i][j] + bg[n-512]);
        }
    }
}

// ---------------- attention step (scores, softmax, ctx), 512 threads ----------
__global__ __launch_bounds__(512) void attn_kernel(int t,
        const float* __restrict__ wf, const float* __restrict__ bf_scalar,
        float* __restrict__ out_alphas) {
    int b = blockIdx.x;
    if (t >= d_declen[b]) return;
    int tid  = threadIdx.x;
    int lane = tid & 31, warp = tid >> 5;

    __shared__ float4 s_da[128], s_wf[128];
    __shared__ float sc[NPIX];
    __shared__ float red_m[16], red_s[16], bc[2];

    if (tid < 128) {
        s_da[tid] = ((const float4*)d_da)[b*128 + tid];
        s_wf[tid] = ((const float4*)wf)[tid];
    }
    __syncthreads();

    const float4* ea4 = ((const float4*)d_ea) + (size_t)b*NPIX*128;
    float bfull = bf_scalar[0];
    for (int p = warp; p < NPIX; p += 16) {
        float s = 0.f;
        #pragma unroll
        for (int j = 0; j < 4; j++) {
            int k4 = lane + j*32;
            float4 e = ea4[p*128 + k4];
            float4 da = s_da[k4];
            float4 w  = s_wf[k4];
            s += fmaxf(e.x + da.x, 0.f) * w.x;
            s += fmaxf(e.y + da.y, 0.f) * w.y;
            s += fmaxf(e.z + da.z, 0.f) * w.z;
            s += fmaxf(e.w + da.w, 0.f) * w.w;
        }
        s = warp_sum(s);
        if (lane == 0) sc[p] = s + bfull;
    }
    __syncthreads();

    float v = (tid < NPIX) ? sc[tid] : -1e30f;
    float wm = warp_max(v);
    if (lane == 0) red_m[warp] = wm;
    __syncthreads();
    if (tid == 0) {
        float mm = red_m[0];
        #pragma unroll
        for (int i = 1; i < 16; i++) mm = fmaxf(mm, red_m[i]);
        bc[0] = mm;
    }
    __syncthreads();
    float gmax = bc[0];
    float e = (tid < NPIX) ? __expf(v - gmax) : 0.f;
    float ws = warp_sum(e);
    if (lane == 0) red_s[warp] = ws;
    __syncthreads();
    if (tid == 0) {
        float ss = 0.f;
        #pragma unroll
        for (int i = 0; i < 16; i++) ss += red_s[i];
        bc[1] = ss;
    }
    __syncthreads();
    float alpha = e / bc[1];
    __syncthreads();
    if (tid < NPIX) {
        sc[tid] = alpha;
        out_alphas[(size_t)b*TT*NPIX + (size_t)t*NPIX + tid] = alpha;
    }
    __syncthreads();

    const float* encb = d_enc_s + (size_t)b*NPIX*512;
    float a0 = 0.f, a1 = 0.f, a2 = 0.f, a3 = 0.f;
    #pragma unroll 4
    for (int p = 0; p < 196; p += 4) {
        a0 += sc[p]   * encb[(p)  *512 + tid];
        a1 += sc[p+1] * encb[(p+1)*512 + tid];
        a2 += sc[p+2] * encb[(p+2)*512 + tid];
        a3 += sc[p+3] * encb[(p+3)*512 + tid];
    }
    d_ctx[b*512 + tid] = ((a0 + a1) + (a2 + a3)) * d_gate[b*512 + tid];
}

// ---------------- LSTM gate GEMM (split-K x8): partials -----------------------
__global__ __launch_bounds__(256) void lstm_gemm_kernel(int t, int hb,
        const float* __restrict__ emb, const float* __restrict__ Wih,
        const float* __restrict__ Whh) {
    __shared__ float sA[32][64];
    __shared__ float sW[32][64];
    __shared__ int   stok[64];
    const float* hsrc = d_hbuf[hb];
    int tid = threadIdx.x;
    if (tid < 64) stok[tid] = d_caps_s[tid*ML + t];
    __syncthreads();
    int tx = tid & 15, ty = tid >> 4;
    int n0 = blockIdx.x * 64;
    int kbase = blockIdx.y * 192;
    float acc[4][4] = {};
    for (int k0 = kbase; k0 < kbase + 192; k0 += 32) {
        #pragma unroll
        for (int u = 0; u < 2; u++) {
            int f4i = tid + u*256;
            int m  = f4i >> 3;
            int kk = (f4i & 7) << 2;
            int k  = k0 + kk;
            float4 a;
            if (k < 512)       a = *(const float4*)&emb[(size_t)stok[m]*512 + k];
            else if (k < 1024) a = *(const float4*)&d_ctx[m*512 + (k - 512)];
            else               a = *(const float4*)&hsrc[m*512 + (k - 1024)];
            sA[kk][m] = a.x; sA[kk+1][m] = a.y; sA[kk+2][m] = a.z; sA[kk+3][m] = a.w;
            float4 w;
            if (k < 1024) w = *(const float4*)&Wih[(size_t)(n0+m)*1024 + k];
            else          w = *(const float4*)&Whh[(size_t)(n0+m)*512 + (k - 1024)];
            sW[kk][m] = w.x; sW[kk+1][m] = w.y; sW[kk+2][m] = w.z; sW[kk+3][m] = w.w;
        }
        __syncthreads();
        #pragma unroll
        for (int k = 0; k < 32; k++) {
            float4 a = *(const float4*)&sA[k][ty*4];
            float4 w = *(const float4*)&sW[k][tx*4];
            float av[4] = {a.x, a.y, a.z, a.w};
            float wv[4] = {w.x, w.y, w.z, w.w};
            #pragma unroll
            for (int i = 0; i < 4; i++)
                #pragma unroll
                for (int j = 0; j < 4; j++)
                    acc[i][j] += av[i] * wv[j];
        }
        __syncthreads();
    }
    float* gp = d_gates_p + (size_t)blockIdx.y * (BSZ*2048);
    #pragma unroll
    for (int i = 0; i < 4; i++) {
        int m = ty*4 + i;
        #pragma unroll
        for (int j = 0; j < 4; j++) {
            int n = n0 + tx*4 + j;
            gp[m*2048 + n] = acc[i][j];
        }
    }
}

// ---------------- fused: LSTM apply + dagate (16 blocks, grid spin-barrier) ---
__global__ __launch_bounds__(256) void fused_apply_dagate(int hbw,
        const float* __restrict__ bih, const float* __restrict__ bhh,
        const float* __restrict__ Wd, const float* __restrict__ bd,
        const float* __restrict__ Wg, const float* __restrict__ bg) {
    int tid = threadIdx.x;
    // ---- phase 1: apply, 8 consecutive elements per thread -------------------
    {
        int gid = blockIdx.x*256 + tid;        // 4096 threads total
        int idx0 = gid*8;
        int b = idx0 >> 9;
        int f0 = (idx0 & 511) >> 2;            // float4 index within 512
        float acc[4][8];
        #pragma unroll
        for (int q = 0; q < 4; q++)
            #pragma unroll
            for (int e = 0; e < 8; e++) acc[q][e] = 0.f;
        #pragma unroll
        for (int s = 0; s < NSPLIT; s++) {
            const float4* g4 = (const float4*)(d_gates_p + (size_t)s*(BSZ*2048) + b*2048);
            #pragma unroll
            for (int q = 0; q < 4; q++) {
                float4 v0 = g4[q*128 + f0];
                float4 v1 = g4[q*128 + f0 + 1];
                acc[q][0] += v0.x; acc[q][1] += v0.y; acc[q][2] += v0.z; acc[q][3] += v0.w;
                acc[q][4] += v1.x; acc[q][5] += v1.y; acc[q][6] += v1.z; acc[q][7] += v1.w;
            }
        }
        const float4* bi4 = (const float4*)bih;
        const float4* bh4 = (const float4*)bhh;
        #pragma unroll
        for (int q = 0; q < 4; q++) {
            float4 u0 = bi4[q*128 + f0], u1 = bi4[q*128 + f0 + 1];
            float4 w0 = bh4[q*128 + f0], w1 = bh4[q*128 + f0 + 1];
            acc[q][0] += u0.x + w0.x; acc[q][1] += u0.y + w0.y;
            acc[q][2] += u0.z + w0.z; acc[q][3] += u0.w + w0.w;
            acc[q][4] += u1.x + w1.x; acc[q][5] += u1.y + w1.y;
            acc[q][6] += u1.z + w1.z; acc[q][7] += u1.w + w1.w;
        }
        float hv[8];
        #pragma unroll
        for (int e = 0; e < 8; e++) {
            float ig = sigmoidf_(acc[0][e]);
            float fg = sigmoidf_(acc[1][e]);
            float g2 = tanhf(acc[2][e]);
            float og = sigmoidf_(acc[3][e]);
            float c  = fg * d_c[idx0 + e] + ig * g2;
            float h  = og * tanhf(c);
            d_c[idx0 + e] = c;
            hv[e] = h;
        }
        float* hout = d_hbuf[hbw] + idx0;
        *(float4*)hout       = make_float4(hv[0], hv[1], hv[2], hv[3]);
        *(float4*)(hout + 4) = make_float4(hv[4], hv[5], hv[6], hv[7]);
        uint4 ph, pl;
        bfsplit2(hv[0], hv[1], ph.x, pl.x);
        bfsplit2(hv[2], hv[3], ph.y, pl.y);
        bfsplit2(hv[4], hv[5], ph.z, pl.z);
        bfsplit2(hv[6], hv[7], ph.w, pl.w);
        ((uint4*)d_hph[hbw])[gid] = ph;
        ((uint4*)d_hpl[hbw])[gid] = pl;
    }
    // ---- grid barrier (monotonic ticket; replay-safe) ------------------------
    __threadfence();
    __syncthreads();
    if (tid == 0) {
        unsigned t0 = atomicAdd(&d_bar, 1u);
        unsigned target = t0 - (t0 & 15u) + 16u;
        while (atomicAdd(&d_bar, 0u) < target) { }
    }
    __syncthreads();
    // ---- phase 2: dagate on the fresh h --------------------------------------
    {
        __shared__ float sA[32][64];
        __shared__ float sW[32][64];
        const float* hsrc = d_hbuf[hbw];
        int tx = tid & 15, ty = tid >> 4;
        int n0 = blockIdx.x * 64;
        const float* Wmat = (n0 < 512) ? (Wd + (size_t)n0*512) : (Wg + (size_t)(n0-512)*512);
        float acc[4][4] = {};
        for (int k0 = 0; k0 < 512; k0 += 32) {
            #pragma unroll
            for (int u = 0; u < 2; u++) {
                int f4i = tid + u*256;
                int m  = f4i >> 3;
                int kk = (f4i & 7) << 2;
                float4 a = *(const float4*)&hsrc[(size_t)m*512 + k0 + kk];
                sA[kk][m] = a.x; sA[kk+1][m] = a.y; sA[kk+2][m] = a.z; sA[kk+3][m] = a.w;
                float4 w = *(const float4*)&Wmat[(size_t)m*512 + k0 + kk];
                sW[kk][m] = w.x; sW[kk+1][m] = w.y; sW[kk+2][m] = w.z; sW[kk+3][m] = w.w;
            }
            __syncthreads();
            #pragma unroll
            for (int k = 0; k < 32; k++) {
                float4 a = *(const float4*)&sA[k][ty*4];
                float4 w = *(const float4*)&sW[k][tx*4];
                float av[4] = {a.x, a.y, a.z, a.w};
                float wv[4] = {w.x, w.y, w.z, w.w};
                #pragma unroll
                for (int i = 0; i < 4; i++)
                    #pragma unroll
                    for (int j = 0; j < 4; j++)
                        acc[i][j] += av[i] * wv[j];
            }
            __syncthreads();
        }
        #pragma unroll
        for (int i = 0; i < 4; i++) {
            int m = ty*4 + i;
            #pragma unroll
            for (int j = 0; j < 4; j++) {
                int n = n0 + tx*4 + j;
                if (n < 512) d_da[m*512 + n] = acc[i][j] + bd[n];
                else         d_gate[m*512 + (n-512)] = sigmoidf_(acc[i][j] + bg[n-512]);
            }
        }
    }
}

// ---------------- preds: bf16 split mma, cp.async double-buffered -------------
__device__ __forceinline__ void preds_issue(uint32_t* Asm, uint32_t* Wsm,
        int stage, int kt, int n0, int tid, const uint4* hph, const uint4* hpl) {
    uint32_t* As = Asm + stage*(64*36);
    uint32_t* Ws = Wsm + stage*(256*36);
    #pragma unroll
    for (int u = 0; u < 2; u++) {      // A: 64 rows x 8 chunks (4 hi + 4 lo)
        int cid = tid + u*256;
        int row = cid >> 3, c = cid & 7;
        const uint4* src = (c < 4) ? (hph + row*64 + kt*4 + c)
                                   : (hpl + row*64 + kt*4 + (c - 4));
        uint32_t* dst = As + row*36 + ((c < 4) ? c*4 : 16 + (c - 4)*4);
        __pipeline_memcpy_async(dst, src, 16);
    }
    const uint4* wh = (const uint4*)d_wfh16;
    const uint4* wl = (const uint4*)d_wfl16;
    #pragma unroll
    for (int u = 0; u < 8; u++) {      // W: 256 rows x 8 chunks
        int cid = tid + u*256;
        int row = cid >> 3, c = cid & 7;
        const uint4* src = (c < 4) ? (wh + (size_t)(n0 + row)*64 + kt*4 + c)
                                   : (wl + (size_t)(n0 + row)*64 + kt*4 + (c - 4));
        uint32_t* dst = Ws + row*36 + ((c < 4) ? c*4 : 16 + (c - 4)*4);
        __pipeline_memcpy_async(dst, src, 16);
    }
    __pipeline_commit();
}

__global__ __launch_bounds__(256) void preds_kernel(int t, int hb,
        const float* __restrict__ bfc, float* __restrict__ out_pred) {
    int nact = d_nact[t];
    if (nact == 0) return;
    extern __shared__ uint32_t sm[];
    uint32_t* Asm = sm;                  // [2][64*36]
    uint32_t* Wsm = sm + 2*64*36;        // [2][256*36]

    int n0 = blockIdx.x * 256;
    int tid = threadIdx.x;
    int lane = tid & 31, wp = tid >> 5;
    int g = lane >> 2, tig = lane & 3;
    const uint4* hph = (const uint4*)d_hph[hb];
    const uint4* hpl = (const uint4*)d_hpl[hb];

    float acc[4][4][4];
    #pragma unroll
    for (int a = 0; a < 4; a++)
        #pragma unroll
        for (int b2 = 0; b2 < 4; b2++)
            #pragma unroll
            for (int c2 = 0; c2 < 4; c2++) acc[a][b2][c2] = 0.f;

    preds_issue(Asm, Wsm, 0, 0, n0, tid, hph, hpl);
    for (int kt = 0; kt < 16; kt++) {
        int stage = kt & 1;
        if (kt < 15) {
            preds_issue(Asm, Wsm, stage ^ 1, kt + 1, n0, tid, hph, hpl);
            __pipeline_wait_prior(1);
        } else {
            __pipeline_wait_prior(0);
        }
        __syncthreads();
        const uint32_t* Ahs = Asm + stage*(64*36);
        const uint32_t* Whs = Wsm + stage*(256*36);
        #pragma unroll
        for (int ks = 0; ks < 2; ks++) {
            int ko = ks*8 + tig;
            uint32_t ah[4][4], al[4][4];
            #pragma unroll
            for (int mf = 0; mf < 4; mf++) {
                int r0 = (mf*16 + g)*36, r1 = (mf*16 + g + 8)*36;
                ah[mf][0] = Ahs[r0 + ko];      ah[mf][1] = Ahs[r1 + ko];
                ah[mf][2] = Ahs[r0 + ko + 4];  ah[mf][3] = Ahs[r1 + ko + 4];
                al[mf][0] = Ahs[r0 + 16 + ko];     al[mf][1] = Ahs[r1 + 16 + ko];
                al[mf][2] = Ahs[r0 + 16 + ko + 4]; al[mf][3] = Ahs[r1 + 16 + ko + 4];
            }
            #pragma unroll
            for (int nf = 0; nf < 4; nf++) {
                int rw = (wp*32 + nf*8 + g)*36 + ko;
                uint32_t bh0 = Whs[rw], bh1 = Whs[rw + 4];
                uint32_t bl0 = Whs[rw + 16], bl1 = Whs[rw + 20];
                #pragma unroll
                for (int mf = 0; mf < 4; mf++) {
                    mma_bf16(acc[mf][nf], ah[mf][0], ah[mf][1], ah[mf][2], ah[mf][3], bh0, bh1);
                    mma_bf16(acc[mf][nf], al[mf][0], al[mf][1], al[mf][2], al[mf][3], bh0, bh1);
                    mma_bf16(acc[mf][nf], ah[mf][0], ah[mf][1], ah[mf][2], ah[mf][3], bl0, bl1);
                }
            }
        }
        __syncthreads();
    }

    size_t tbase = (size_t)t * VV;
    #pragma unroll
    for (int nf = 0; nf < 4; nf++) {
        int n = n0 + wp*32 + nf*8 + 2*tig;
        float2 bb = *(const float2*)&bfc[n];
        #pragma unroll
        for (int mf = 0; mf < 4; mf++) {
            int m1 = mf*16 + g;
            if (m1 < nact) {
                float2 o; o.x = acc[mf][nf][0] + bb.x; o.y = acc[mf][nf][1] + bb.y;
                *(float2*)&out_pred[(size_t)m1*((size_t)TT*VV) + tbase + n] = o;
            }
            int m2 = m1 + 8;
            if (m2 < nact) {
                float2 o; o.x = acc[mf][nf][2] + bb.x; o.y = acc[mf][nf][3] + bb.y;
                *(float2*)&out_pred[(size_t)m2*((size_t)TT*VV) + tbase + n] = o;
            }
        }
    }
}

// ---------------- launch ------------------------------------------------------
extern "C" void kernel_launch(void* const* d_in, const int* in_sizes, int n_in,
                              void* d_out, int out_size) {
    const float* encoder_out = (const float*)d_in[0];
    const int*   caps        = (const int*)  d_in[1];
    const int*   cap_len     = (const int*)  d_in[2];
    const float* W_enc_attn  = (const float*)d_in[3];
    const float* b_enc_attn  = (const float*)d_in[4];
    const float* W_dec_attn  = (const float*)d_in[5];
    const float* b_dec_attn  = (const float*)d_in[6];
    const float* w_full_attn = (const float*)d_in[7];
    const float* b_full_attn = (const float*)d_in[8];
    const float* emb_table   = (const float*)d_in[9];
    const float* W_ih        = (const float*)d_in[10];
    const float* W_hh        = (const float*)d_in[11];
    const float* b_ih        = (const float*)d_in[12];
    const float* b_hh        = (const float*)d_in[13];
    const float* W_init_h    = (const float*)d_in[14];
    const float* b_init_h    = (const float*)d_in[15];
    const float* W_init_c    = (const float*)d_in[16];
    const float* b_init_c    = (const float*)d_in[17];
    const float* W_f_beta    = (const float*)d_in[18];
    const float* b_f_beta    = (const float*)d_in[19];
    const float* W_fc        = (const float*)d_in[20];
    const float* b_fc        = (const float*)d_in[21];

    float* out = (float*)d_out;
    const size_t OFF_PRED   = 0;
    const size_t OFF_CAPS   = OFF_PRED + (size_t)BSZ*TT*VV;
    const size_t OFF_DECLEN = OFF_CAPS + (size_t)BSZ*ML;
    const size_t OFF_ALPHA  = OFF_DECLEN + BSZ;
    const size_t OFF_ORDER  = OFF_ALPHA + (size_t)BSZ*TT*NPIX;
    float* out_pred   = out + OFF_PRED;
    float* out_caps   = out + OFF_CAPS;
    float* out_declen = out + OFF_DECLEN;
    float* out_alphas = out + OFF_ALPHA;
    float* out_order  = out + OFF_ORDER;

    static cudaStream_t s1 = nullptr, s2 = nullptr;
    static cudaEvent_t evFork, evEnd1, evEnd2;
    static cudaEvent_t evH[TT], evP[TT];
    static bool inited = false;
    const int PREDS_SMEM = (2*64*36 + 2*256*36) * 4;   // 92160 B
    if (!inited) {
        cudaStreamCreateWithFlags(&s1, cudaStreamNonBlocking);
        cudaStreamCreateWithFlags(&s2, cudaStreamNonBlocking);
        cudaEventCreateWithFlags(&evFork, cudaEventDisableTiming);
        cudaEventCreateWithFlags(&evEnd1, cudaEventDisableTiming);
        cudaEventCreateWithFlags(&evEnd2, cudaEventDisableTiming);
        for (int i = 0; i < TT; i++) {
            cudaEventCreateWithFlags(&evH[i], cudaEventDisableTiming);
            cudaEventCreateWithFlags(&evP[i], cudaEventDisableTiming);
        }
        cudaFuncSetAttribute(preds_kernel, cudaFuncAttributeMaxDynamicSharedMemorySize,
                             PREDS_SMEM);
        inited = true;
    }

    cudaMemsetAsync(d_out, 0, (size_t)out_size * sizeof(float));

    convert_wfc_kernel<<<(VV*64)/256, 256>>>((const float4*)W_fc);
    sort_kernel<<<1, 64>>>(cap_len, caps, out_caps, out_declen, out_order);
    reorder_mean_kernel<<<BSZ, 256>>>(encoder_out);
    gemm64_kernel<<<dim3(8, 196), 256>>>(0, W_enc_attn, b_enc_attn, 512, 512);
    gemm64_kernel<<<dim3(8, 1), 256>>>(1, W_init_h, b_init_h, 512, 512);
    gemm64_kernel<<<dim3(8, 1), 256>>>(2, W_init_c, b_init_c, 512, 512);
    convert_h0_kernel<<<64, 256>>>();
    dagate_kernel<<<16, 256>>>(0, W_dec_attn, b_dec_attn, W_f_beta, b_f_beta);

    cudaEventRecord(evFork, 0);
    cudaStreamWaitEvent(s1, evFork, 0);
    cudaStreamWaitEvent(s2, evFork, 0);

    for (int t = 0; t < TT; t++) {
        int hb  = t & 1;          // h_t
        int hbw = (t + 1) & 1;    // h_{t+1}
        attn_kernel<<<BSZ, 512, 0, s1>>>(t, w_full_attn, b_full_attn, out_alphas);
        lstm_gemm_kernel<<<dim3(32, NSPLIT), 256, 0, s1>>>(t, hb, emb_table, W_ih, W_hh);
        if (t >= 2) cudaStreamWaitEvent(s1, evP[t-2], 0);   // WAR vs preds(t-2)
        fused_apply_dagate<<<16, 256, 0, s1>>>(hbw, b_ih, b_hh,
                                               W_dec_attn, b_dec_attn, W_f_beta, b_f_beta);
        cudaEventRecord(evH[t], s1);

        cudaStreamWaitEvent(s2, evH[t], 0);
        preds_kernel<<<VV/256, 256, PREDS_SMEM, s2>>>(t, hbw, b_fc, out_pred);
        cudaEventRecord(evP[t], s2);
    }

    cudaEventRecord(evEnd1, s1);
    cudaEventRecord(evEnd2, s2);
    cudaStreamWaitEvent((cudaStream_t)0, evEnd1, 0);
    cudaStreamWaitEvent((cudaStream_t)0, evEnd2, 0);
}